// round 5
// baseline (speedup 1.0000x reference)
#include <cuda_runtime.h>
#include <cuda_fp16.h>
#include <math_constants.h>
#include <cstdint>

#define BB 4
#define NN 4096
#define DD 256

// ---------------- device scratch (allocation-free rule) ----------------
__device__ __align__(128) __half g_Qhi[(size_t)BB*NN*DD];   // [b][n][d]
__device__ __align__(128) __half g_Qlo[(size_t)BB*NN*DD];
__device__ __align__(128) __half g_Khi[(size_t)BB*NN*DD];   // [b][n][d]
__device__ __align__(128) __half g_Klo[(size_t)BB*NN*DD];
__device__ __align__(128) __half g_Vthi[(size_t)BB*DD*NN];  // [b][d][key]
__device__ __align__(128) __half g_Vtlo[(size_t)BB*DD*NN];
__device__ __align__(128) __half g_Phi[(size_t)BB*NN*NN];   // [b][q][key]
__device__ __align__(128) __half g_Plo[(size_t)BB*NN*NN];
__device__ __align__(128) float  g_S [(size_t)BB*NN*NN];    // [b][q][key]

// ---------------- helpers ----------------
__device__ __forceinline__ uint32_t smem_u32(const void* p) {
    uint32_t a;
    asm("{ .reg .u64 t; cvta.to.shared.u64 t, %1; cvt.u32.u64 %0, t; }" : "=r"(a) : "l"(p));
    return a;
}

#define LDM4(r, addr) asm volatile( \
    "ldmatrix.sync.aligned.m8n8.x4.shared.b16 {%0,%1,%2,%3}, [%4];" \
    : "=r"((r)[0]), "=r"((r)[1]), "=r"((r)[2]), "=r"((r)[3]) : "r"(addr))

// fp32-accumulate MMA (hi*hi term)
#define MMA16816F(c, a, b0, b1) asm volatile( \
    "mma.sync.aligned.m16n8k16.row.col.f32.f16.f16.f32 " \
    "{%0,%1,%2,%3}, {%4,%5,%6,%7}, {%8,%9}, {%0,%1,%2,%3};" \
    : "+f"((c)[0]), "+f"((c)[1]), "+f"((c)[2]), "+f"((c)[3]) \
    : "r"((a)[0]), "r"((a)[1]), "r"((a)[2]), "r"((a)[3]), "r"(b0), "r"(b1))

// fp16-accumulate MMA (cross terms, 2x rate)
#define MMA16816H(c, a, b0, b1) asm volatile( \
    "mma.sync.aligned.m16n8k16.row.col.f16.f16.f16.f16 " \
    "{%0,%1}, {%2,%3,%4,%5}, {%6,%7}, {%0,%1};" \
    : "+r"((c)[0]), "+r"((c)[1]) \
    : "r"((a)[0]), "r"((a)[1]), "r"((a)[2]), "r"((a)[3]), "r"(b0), "r"(b1))

#define CP16(so, ga) asm volatile("cp.async.cg.shared.global [%0], [%1], 16;" \
    :: "r"(so), "l"(ga) : "memory")
#define CP_COMMIT() asm volatile("cp.async.commit_group;" ::: "memory")
#define CP_WAIT2()  asm volatile("cp.async.wait_group 2;" ::: "memory")

// 64B-pitch tile with xor swizzle on 16B chunks: conflict-free for ldmatrix + cp.async
__device__ __forceinline__ uint32_t swz(uint32_t tile, int row, int chunk) {
    return tile + (uint32_t)row * 64u + ((uint32_t)((chunk ^ ((row >> 1) & 3)) & 3) << 4);
}

#define TILE_B   8192u     // 128 rows x 64B
#define STAGE_B  32768u    // Ahi, Alo, Bhi, Blo
#define NSTAGE   4
#define SMEM_SZ  (NSTAGE * 32768)

// ---------------------------------------------------------------------------
// Unified split-fp16 HMMA GEMM (TN): C[128,128](fp32) = A(128,K) . B(128,K)^T
// A ~ Ahi+Alo, B ~ Bhi+Blo; hh in fp32 acc, hl+lh in shared fp16 acc.
// mode 0: QK -> g_S.   mode 1: AV -> out (B,D,N).
// ---------------------------------------------------------------------------
__global__ __launch_bounds__(256, 1) void hmma_kernel(int mode, float* __restrict__ outp)
{
    extern __shared__ __align__(128) char sm[];
    const int tid  = threadIdx.x;
    const int lane = tid & 31, wid = tid >> 5;
    const int wm = wid & 3, wn = wid >> 2;
    const int bx = blockIdx.x, by = blockIdx.y, bz = blockIdx.z;

    const __half *Ahi, *Alo, *Bhi, *Blo;
    float* C;
    size_t lda, ldb;
    int nchunks;
    if (mode == 0) {
        size_t ab = ((size_t)bz * NN + (size_t)by * 128) * DD;
        size_t bb = ((size_t)bz * NN + (size_t)bx * 128) * DD;
        Ahi = g_Qhi + ab;  Alo = g_Qlo + ab;
        Bhi = g_Khi + bb;  Blo = g_Klo + bb;
        C = g_S + (size_t)bz * NN * NN + (size_t)by * 128 * NN + (size_t)bx * 128;
        lda = DD; ldb = DD; nchunks = DD / 32;       // 8
    } else {
        size_t ab = (size_t)bz * DD * NN + (size_t)by * 128 * NN;
        size_t bb = (size_t)bz * NN * NN + (size_t)bx * 128 * NN;
        Ahi = g_Vthi + ab; Alo = g_Vtlo + ab;
        Bhi = g_Phi  + bb; Blo = g_Plo  + bb;
        C = outp + (size_t)bz * DD * NN + (size_t)by * 128 * NN + (size_t)bx * 128;
        lda = NN; ldb = NN; nchunks = NN / 32;       // 128
    }

    const uint32_t sbase = smem_u32(sm);

    auto load_stage = [&](int s, int ch) {
        uint32_t st = sbase + (uint32_t)s * STAGE_B;
        size_t k0 = (size_t)ch * 32;
        const __half* gp[4] = { Ahi + k0, Alo + k0, Bhi + k0, Blo + k0 };
        #pragma unroll
        for (int t2 = 0; t2 < 4; ++t2) {
            uint32_t tb = st + (uint32_t)t2 * TILE_B;
            size_t ld = (t2 < 2) ? lda : ldb;
            const __half* g = gp[t2];
            #pragma unroll
            for (int i = 0; i < 2; ++i) {
                int id = tid + i * 256;
                int row = id >> 2, c = id & 3;
                CP16(swz(tb, row, c), g + (size_t)row * ld + c * 8);
            }
        }
    };

    float    accf[2][8][4] = {};
    uint32_t acch[2][8][2];
    #pragma unroll
    for (int mt = 0; mt < 2; ++mt)
        #pragma unroll
        for (int n8 = 0; n8 < 8; ++n8) { acch[mt][n8][0] = 0u; acch[mt][n8][1] = 0u; }

    auto compute = [&](int s) {
        uint32_t st  = sbase + (uint32_t)s * STAGE_B;
        uint32_t tAh = st, tAl = st + TILE_B, tBh = st + 2*TILE_B, tBl = st + 3*TILE_B;
        #pragma unroll
        for (int ks = 0; ks < 2; ++ks) {
            uint32_t ah[2][4], al[2][4], bh[4][4], bl[4][4];
            const int arow = wm * 32 + (lane & 15);
            const int achk = ks * 2 + (lane >> 4);
            #pragma unroll
            for (int mt = 0; mt < 2; ++mt) {
                LDM4(ah[mt], swz(tAh, arow + mt * 16, achk));
                LDM4(al[mt], swz(tAl, arow + mt * 16, achk));
            }
            const int brow = wn * 64 + ((lane >> 4) << 3) + (lane & 7);
            const int bchk = ks * 2 + ((lane >> 3) & 1);
            #pragma unroll
            for (int nt = 0; nt < 4; ++nt) {
                LDM4(bh[nt], swz(tBh, brow + nt * 16, bchk));
                LDM4(bl[nt], swz(tBl, brow + nt * 16, bchk));
            }
            #pragma unroll
            for (int mt = 0; mt < 2; ++mt)
                #pragma unroll
                for (int n8 = 0; n8 < 8; ++n8) {
                    const int g = n8 >> 1, h = (n8 & 1) * 2;
                    MMA16816F(accf[mt][n8], ah[mt], bh[g][h], bh[g][h+1]);  // hi*hi (fp32)
                    MMA16816H(acch[mt][n8], ah[mt], bl[g][h], bl[g][h+1]);  // hi*lo (fp16)
                    MMA16816H(acch[mt][n8], al[mt], bh[g][h], bh[g][h+1]);  // lo*hi (fp16)
                }
        }
    };

    // prologue: 3 stages in flight
    load_stage(0, 0); CP_COMMIT();
    load_stage(1, 1); CP_COMMIT();
    load_stage(2, 2); CP_COMMIT();

    for (int ch = 0; ch < nchunks; ++ch) {
        CP_WAIT2();            // chunk ch arrived
        __syncthreads();       // all warps done with stage (ch+3)%NSTAGE's old data
        if (ch + 3 < nchunks) load_stage((ch + 3) & (NSTAGE - 1), ch + 3);
        CP_COMMIT();
        compute(ch & (NSTAGE - 1));
    }

    // epilogue: fp32 = accf + tofloat(acch), 32B-coalesced segments
    const int r0 = wm * 32 + (lane >> 2);
    const int c0 = wn * 64 + (lane & 3) * 2;
    #pragma unroll
    for (int mt = 0; mt < 2; ++mt)
        #pragma unroll
        for (int n8 = 0; n8 < 8; ++n8) {
            float2 x0 = __half22float2(*(__half2*)&acch[mt][n8][0]);
            float2 x1 = __half22float2(*(__half2*)&acch[mt][n8][1]);
            float* p = C + (size_t)(r0 + mt * 16) * NN + c0 + n8 * 8;
            *(float2*)p            = make_float2(accf[mt][n8][0] + x0.x, accf[mt][n8][1] + x0.y);
            *(float2*)(p + 8 * NN) = make_float2(accf[mt][n8][2] + x1.x, accf[mt][n8][3] + x1.y);
        }
}

// ---------------------------------------------------------------------------
__device__ __forceinline__ void split8h(const float* v, uint4& uh, uint4& ul) {
    __half2 h[4], l[4];
    #pragma unroll
    for (int j = 0; j < 4; ++j) {
        float a = v[2*j], b = v[2*j+1];
        __half ha = __float2half_rn(a), hb = __float2half_rn(b);
        __half la = __float2half_rn(a - __half2float(ha));
        __half lb = __float2half_rn(b - __half2float(hb));
        h[j] = __halves2half2(ha, hb);
        l[j] = __halves2half2(la, lb);
    }
    uh = *(uint4*)h; ul = *(uint4*)l;
}

// Kernel 1: fused QKV projection (SIMT fp32), fp16 hi/lo epilogues.
__global__ __launch_bounds__(256, 2) void proj_kernel(
    const float* __restrict__ x,
    const float* __restrict__ Wq, const float* __restrict__ bq,
    const float* __restrict__ Wk, const float* __restrict__ bk,
    const float* __restrict__ Wv, const float* __restrict__ bv)
{
    __shared__ float As[16][132];
    __shared__ float Bs[16][132];

    const int bz = blockIdx.z;
    const int b  = bz / 3;
    const int w  = bz % 3;
    const float* W    = (w == 0) ? Wq : ((w == 1) ? Wk : Wv);
    const float* bias = (w == 0) ? bq : ((w == 1) ? bk : bv);

    const int m0 = blockIdx.x * 128;
    const int d0 = blockIdx.y * 128;
    const int tid = threadIdx.x;
    const int tx = tid & 15, ty = tid >> 4;
    const float* Abase = x + (size_t)b * DD * NN;

    float acc[8][8] = {};
    float4 pa[2], pb[2];
    #pragma unroll
    for (int u = 0; u < 2; ++u) {
        int idx = tid + u * 256;
        int kl = idx >> 5, m4 = (idx & 31) << 2;
        pa[u] = *(const float4*)(Abase + (size_t)kl * NN + m0 + m4);
        pb[u] = *(const float4*)(W     + (size_t)kl * DD + d0 + m4);
    }
    for (int kc = 0; kc < DD; kc += 16) {
        #pragma unroll
        for (int u = 0; u < 2; ++u) {
            int idx = tid + u * 256;
            int kl = idx >> 5, m4 = (idx & 31) << 2;
            *(float4*)&As[kl][m4] = pa[u];
            *(float4*)&Bs[kl][m4] = pb[u];
        }
        __syncthreads();
        if (kc + 16 < DD) {
            int kn = kc + 16;
            #pragma unroll
            for (int u = 0; u < 2; ++u) {
                int idx = tid + u * 256;
                int kl = idx >> 5, m4 = (idx & 31) << 2;
                pa[u] = *(const float4*)(Abase + (size_t)(kn + kl) * NN + m0 + m4);
                pb[u] = *(const float4*)(W     + (size_t)(kn + kl) * DD + d0 + m4);
            }
        }
        #pragma unroll
        for (int kk = 0; kk < 16; ++kk) {
            float a[8], bb[8];
            *(float4*)&a[0]  = *(float4*)&As[kk][ty * 8];
            *(float4*)&a[4]  = *(float4*)&As[kk][ty * 8 + 4];
            *(float4*)&bb[0] = *(float4*)&Bs[kk][tx * 8];
            *(float4*)&bb[4] = *(float4*)&Bs[kk][tx * 8 + 4];
            #pragma unroll
            for (int i = 0; i < 8; ++i)
                #pragma unroll
                for (int j = 0; j < 8; ++j)
                    acc[i][j] += a[i] * bb[j];
        }
        __syncthreads();
    }

    if (w < 2) {  // Q/K row-major [n][d]
        __half* Oh = ((w == 0) ? g_Qhi : g_Khi) + (size_t)b * NN * DD;
        __half* Ol = ((w == 0) ? g_Qlo : g_Klo) + (size_t)b * NN * DD;
        #pragma unroll
        for (int i = 0; i < 8; ++i) {
            int n = m0 + ty * 8 + i, d = d0 + tx * 8;
            float v[8];
            #pragma unroll
            for (int j = 0; j < 8; ++j) v[j] = acc[i][j] + bias[d + j];
            uint4 uh, ul; split8h(v, uh, ul);
            *(uint4*)(Oh + (size_t)n * DD + d) = uh;
            *(uint4*)(Ol + (size_t)n * DD + d) = ul;
        }
    } else {      // V transposed [d][n]
        __half* Oh = g_Vthi + (size_t)b * DD * NN;
        __half* Ol = g_Vtlo + (size_t)b * DD * NN;
        #pragma unroll
        for (int j = 0; j < 8; ++j) {
            int d = d0 + tx * 8 + j;
            float bb = bias[d];
            float v[8];
            #pragma unroll
            for (int i = 0; i < 8; ++i) v[i] = acc[i][j] + bb;
            uint4 uh, ul; split8h(v, uh, ul);
            *(uint4*)(Oh + (size_t)d * NN + m0 + ty * 8) = uh;
            *(uint4*)(Ol + (size_t)d * NN + m0 + ty * 8) = ul;
        }
    }
}

// Kernel 3: row softmax, fp32 S in, fp16 hi/lo P out.
__inline__ __device__ float warpMax(float v) {
    #pragma unroll
    for (int o = 16; o; o >>= 1) v = fmaxf(v, __shfl_xor_sync(0xffffffffu, v, o));
    return v;
}
__inline__ __device__ float warpSum(float v) {
    #pragma unroll
    for (int o = 16; o; o >>= 1) v += __shfl_xor_sync(0xffffffffu, v, o);
    return v;
}

__global__ __launch_bounds__(256) void softmax_kernel()
{
    __shared__ float red[8];
    const size_t row = blockIdx.x;
    const float* p = g_S + row * (size_t)NN;
    __half* ph = g_Phi + row * (size_t)NN;
    __half* pl = g_Plo + row * (size_t)NN;
    const int tid = threadIdx.x;
    const int lane = tid & 31, wid = tid >> 5;

    float4 v[4];
    float m = -CUDART_INF_F;
    #pragma unroll
    for (int u = 0; u < 4; ++u) {
        v[u] = *(const float4*)(p + (size_t)(tid + u * 256) * 4);
        m = fmaxf(m, fmaxf(fmaxf(v[u].x, v[u].y), fmaxf(v[u].z, v[u].w)));
    }
    m = warpMax(m);
    if (lane == 0) red[wid] = m;
    __syncthreads();
    float bm = red[0];
    #pragma unroll
    for (int i = 1; i < 8; ++i) bm = fmaxf(bm, red[i]);
    __syncthreads();

    float s = 0.f;
    #pragma unroll
    for (int u = 0; u < 4; ++u) {
        v[u].x = __expf(v[u].x - bm); v[u].y = __expf(v[u].y - bm);
        v[u].z = __expf(v[u].z - bm); v[u].w = __expf(v[u].w - bm);
        s += v[u].x + v[u].y + v[u].z + v[u].w;
    }
    s = warpSum(s);
    if (lane == 0) red[wid] = s;
    __syncthreads();
    float tot = 0.f;
    #pragma unroll
    for (int i = 0; i < 8; ++i) tot += red[i];
    float inv = 1.0f / tot;

    #pragma unroll
    for (int u = 0; u < 4; ++u) {
        size_t idx = (size_t)(tid + u * 256) * 4;
        float vv[4] = { v[u].x * inv, v[u].y * inv, v[u].z * inv, v[u].w * inv };
        __half h[4]; float lo[4];
        #pragma unroll
        for (int j = 0; j < 4; ++j) {
            h[j] = __float2half_rn(vv[j]);
            lo[j] = vv[j] - __half2float(h[j]);
        }
        *(__half2*)(ph + idx)     = __halves2half2(h[0], h[1]);
        *(__half2*)(ph + idx + 2) = __halves2half2(h[2], h[3]);
        *(__half2*)(pl + idx)     = __halves2half2(__float2half_rn(lo[0]), __float2half_rn(lo[1]));
        *(__half2*)(pl + idx + 2) = __halves2half2(__float2half_rn(lo[2]), __float2half_rn(lo[3]));
    }
}

// ---------------------------------------------------------------------------
extern "C" void kernel_launch(void* const* d_in, const int* in_sizes, int n_in,
                              void* d_out, int out_size)
{
    const float* x  = (const float*)d_in[0];
    const float* Wq = (const float*)d_in[1];
    const float* bq = (const float*)d_in[2];
    const float* Wk = (const float*)d_in[3];
    const float* bk = (const float*)d_in[4];
    const float* Wv = (const float*)d_in[5];
    const float* bv = (const float*)d_in[6];
    float* out = (float*)d_out;

    cudaFuncSetAttribute(hmma_kernel, cudaFuncAttributeMaxDynamicSharedMemorySize, SMEM_SZ);

    proj_kernel<<<dim3(NN / 128, DD / 128, BB * 3), 256>>>(x, Wq, bq, Wk, bk, Wv, bv);
    hmma_kernel<<<dim3(NN / 128, NN / 128, BB), 256, SMEM_SZ>>>(0, nullptr);  // QK -> S
    softmax_kernel<<<BB * NN, 256>>>();
    hmma_kernel<<<dim3(NN / 128, DD / 128, BB), 256, SMEM_SZ>>>(1, out);      // AV -> out
}

// round 6
// speedup vs baseline: 1.0613x; 1.0613x over previous
#include <cuda_runtime.h>
#include <cuda_fp16.h>
#include <math_constants.h>
#include <cstdint>

#define BB 4
#define NN 4096
#define DD 256

// ---------------- device scratch (allocation-free rule) ----------------
__device__ __align__(128) __half g_Qhi[(size_t)BB*NN*DD];   // [b][n][d]
__device__ __align__(128) __half g_Qlo[(size_t)BB*NN*DD];
__device__ __align__(128) __half g_Khi[(size_t)BB*NN*DD];   // [b][n][d]
__device__ __align__(128) __half g_Klo[(size_t)BB*NN*DD];
__device__ __align__(128) __half g_Vthi[(size_t)BB*DD*NN];  // [b][d][key]
__device__ __align__(128) __half g_Vtlo[(size_t)BB*DD*NN];
__device__ __align__(128) __half g_Phi[(size_t)BB*NN*NN];   // [b][q][key]
__device__ __align__(128) __half g_Plo[(size_t)BB*NN*NN];
__device__ __align__(128) float  g_S [(size_t)BB*NN*NN];    // [b][q][key]

// ---------------- helpers ----------------
__device__ __forceinline__ uint32_t smem_u32(const void* p) {
    uint32_t a;
    asm("{ .reg .u64 t; cvta.to.shared.u64 t, %1; cvt.u32.u64 %0, t; }" : "=r"(a) : "l"(p));
    return a;
}

#define LDM4(r, addr) asm volatile( \
    "ldmatrix.sync.aligned.m8n8.x4.shared.b16 {%0,%1,%2,%3}, [%4];" \
    : "=r"((r)[0]), "=r"((r)[1]), "=r"((r)[2]), "=r"((r)[3]) : "r"(addr))

#define MMA16816F(c, a, b0, b1) asm volatile( \
    "mma.sync.aligned.m16n8k16.row.col.f32.f16.f16.f32 " \
    "{%0,%1,%2,%3}, {%4,%5,%6,%7}, {%8,%9}, {%0,%1,%2,%3};" \
    : "+f"((c)[0]), "+f"((c)[1]), "+f"((c)[2]), "+f"((c)[3]) \
    : "r"((a)[0]), "r"((a)[1]), "r"((a)[2]), "r"((a)[3]), "r"(b0), "r"(b1))

#define CP16(so, ga) asm volatile("cp.async.cg.shared.global [%0], [%1], 16;" \
    :: "r"(so), "l"(ga) : "memory")
#define CP_COMMIT() asm volatile("cp.async.commit_group;" ::: "memory")
#define CP_WAIT2()  asm volatile("cp.async.wait_group 2;" ::: "memory")

// 64B-pitch tile with xor swizzle on 16B chunks: conflict-free for ldmatrix + cp.async
__device__ __forceinline__ uint32_t swz(uint32_t tile, int row, int chunk) {
    return tile + (uint32_t)row * 64u + ((uint32_t)((chunk ^ ((row >> 1) & 3)) & 3) << 4);
}

// CTA tile 64(m) x 128(n), K-chunk 32.
#define A_TILE_B 4096u     // 64 rows x 64B
#define B_TILE_B 8192u     // 128 rows x 64B
#define STAGE_B  24576u    // Ahi, Alo, Bhi, Blo
#define NSTAGE   4
#define SMEM_SZ  (NSTAGE * 24576)

// ---------------------------------------------------------------------------
// Unified split-fp16 HMMA GEMM (TN): C[64,128](fp32) = A(64,K) . B(128,K)^T
// A ~ Ahi+Alo, B ~ Bhi+Blo; hh + hl + lh all accumulate into fp32 acc.
// mode 0: QK -> g_S.   mode 1: AV -> out (B,D,N).
// 128 threads, 4 warps (2m x 2n), warp tile 32x64. 2 CTAs/SM.
// ---------------------------------------------------------------------------
__global__ __launch_bounds__(128, 2) void hmma_kernel(int mode, float* __restrict__ outp)
{
    extern __shared__ __align__(128) char sm[];
    const int tid  = threadIdx.x;
    const int lane = tid & 31, wid = tid >> 5;
    const int wm = wid & 1, wn = wid >> 1;
    const int bx = blockIdx.x, by = blockIdx.y, bz = blockIdx.z;

    const __half *Ahi, *Alo, *Bhi, *Blo;
    float* C;
    size_t lda, ldb;
    int nchunks;
    if (mode == 0) {
        size_t ab = ((size_t)bz * NN + (size_t)by * 64) * DD;
        size_t bb = ((size_t)bz * NN + (size_t)bx * 128) * DD;
        Ahi = g_Qhi + ab;  Alo = g_Qlo + ab;
        Bhi = g_Khi + bb;  Blo = g_Klo + bb;
        C = g_S + (size_t)bz * NN * NN + (size_t)by * 64 * NN + (size_t)bx * 128;
        lda = DD; ldb = DD; nchunks = DD / 32;       // 8
    } else {
        size_t ab = (size_t)bz * DD * NN + (size_t)by * 64 * NN;
        size_t bb = (size_t)bz * NN * NN + (size_t)bx * 128 * NN;
        Ahi = g_Vthi + ab; Alo = g_Vtlo + ab;
        Bhi = g_Phi  + bb; Blo = g_Plo  + bb;
        C = outp + (size_t)bz * DD * NN + (size_t)by * 64 * NN + (size_t)bx * 128;
        lda = NN; ldb = NN; nchunks = NN / 32;       // 128
    }

    const uint32_t sbase = smem_u32(sm);

    auto load_stage = [&](int s, int ch) {
        uint32_t st = sbase + (uint32_t)s * STAGE_B;
        size_t k0 = (size_t)ch * 32;
        // A tiles: 64 rows x 4 chunks = 256 cp.asyncs; 2 per thread per tile
        const __half* ga[2] = { Ahi + k0, Alo + k0 };
        #pragma unroll
        for (int t2 = 0; t2 < 2; ++t2) {
            uint32_t tb = st + (uint32_t)t2 * A_TILE_B;
            #pragma unroll
            for (int i = 0; i < 2; ++i) {
                int id = tid + i * 128;
                int row = id >> 2, c = id & 3;
                CP16(swz(tb, row, c), ga[t2] + (size_t)row * lda + c * 8);
            }
        }
        // B tiles: 128 rows x 4 chunks = 512 cp.asyncs; 4 per thread per tile
        const __half* gb[2] = { Bhi + k0, Blo + k0 };
        #pragma unroll
        for (int t2 = 0; t2 < 2; ++t2) {
            uint32_t tb = st + 2 * A_TILE_B + (uint32_t)t2 * B_TILE_B;
            #pragma unroll
            for (int i = 0; i < 4; ++i) {
                int id = tid + i * 128;
                int row = id >> 2, c = id & 3;
                CP16(swz(tb, row, c), gb[t2] + (size_t)row * ldb + c * 8);
            }
        }
    };

    float accf[2][8][4] = {};

    auto compute = [&](int s) {
        uint32_t st  = sbase + (uint32_t)s * STAGE_B;
        uint32_t tAh = st, tAl = st + A_TILE_B;
        uint32_t tBh = st + 2 * A_TILE_B, tBl = tBh + B_TILE_B;
        #pragma unroll
        for (int ks = 0; ks < 2; ++ks) {
            uint32_t ah[2][4], al[2][4], bh[4][4], bl[4][4];
            const int arow = wm * 32 + (lane & 15);
            const int achk = ks * 2 + (lane >> 4);
            #pragma unroll
            for (int mt = 0; mt < 2; ++mt) {
                LDM4(ah[mt], swz(tAh, arow + mt * 16, achk));
                LDM4(al[mt], swz(tAl, arow + mt * 16, achk));
            }
            const int brow = wn * 64 + ((lane >> 4) << 3) + (lane & 7);
            const int bchk = ks * 2 + ((lane >> 3) & 1);
            #pragma unroll
            for (int nt = 0; nt < 4; ++nt) {
                LDM4(bh[nt], swz(tBh, brow + nt * 16, bchk));
                LDM4(bl[nt], swz(tBl, brow + nt * 16, bchk));
            }
            #pragma unroll
            for (int mt = 0; mt < 2; ++mt)
                #pragma unroll
                for (int n8 = 0; n8 < 8; ++n8) {
                    const int g = n8 >> 1, h = (n8 & 1) * 2;
                    MMA16816F(accf[mt][n8], ah[mt], bh[g][h], bh[g][h+1]);  // hi*hi
                    MMA16816F(accf[mt][n8], ah[mt], bl[g][h], bl[g][h+1]);  // hi*lo
                    MMA16816F(accf[mt][n8], al[mt], bh[g][h], bh[g][h+1]);  // lo*hi
                }
        }
    };

    // prologue: 3 stages in flight
    load_stage(0, 0); CP_COMMIT();
    load_stage(1, 1); CP_COMMIT();
    load_stage(2, 2); CP_COMMIT();

    for (int ch = 0; ch < nchunks; ++ch) {
        CP_WAIT2();            // chunk ch arrived
        __syncthreads();       // all warps done with the stage being overwritten
        if (ch + 3 < nchunks) load_stage((ch + 3) & (NSTAGE - 1), ch + 3);
        CP_COMMIT();
        compute(ch & (NSTAGE - 1));
    }

    // epilogue: fp32, 32B-coalesced segments
    const int r0 = wm * 32 + (lane >> 2);
    const int c0 = wn * 64 + (lane & 3) * 2;
    #pragma unroll
    for (int mt = 0; mt < 2; ++mt)
        #pragma unroll
        for (int n8 = 0; n8 < 8; ++n8) {
            float* p = C + (size_t)(r0 + mt * 16) * NN + c0 + n8 * 8;
            *(float2*)p            = make_float2(accf[mt][n8][0], accf[mt][n8][1]);
            *(float2*)(p + 8 * NN) = make_float2(accf[mt][n8][2], accf[mt][n8][3]);
        }
}

// ---------------------------------------------------------------------------
__device__ __forceinline__ void split8h(const float* v, uint4& uh, uint4& ul) {
    __half2 h[4], l[4];
    #pragma unroll
    for (int j = 0; j < 4; ++j) {
        float a = v[2*j], b = v[2*j+1];
        __half ha = __float2half_rn(a), hb = __float2half_rn(b);
        __half la = __float2half_rn(a - __half2float(ha));
        __half lb = __float2half_rn(b - __half2float(hb));
        h[j] = __halves2half2(ha, hb);
        l[j] = __halves2half2(la, lb);
    }
    uh = *(uint4*)h; ul = *(uint4*)l;
}

// Kernel 1: fused QKV projection (SIMT fp32), fp16 hi/lo epilogues.
__global__ __launch_bounds__(256, 2) void proj_kernel(
    const float* __restrict__ x,
    const float* __restrict__ Wq, const float* __restrict__ bq,
    const float* __restrict__ Wk, const float* __restrict__ bk,
    const float* __restrict__ Wv, const float* __restrict__ bv)
{
    __shared__ float As[16][132];
    __shared__ float Bs[16][132];

    const int bz = blockIdx.z;
    const int b  = bz / 3;
    const int w  = bz % 3;
    const float* W    = (w == 0) ? Wq : ((w == 1) ? Wk : Wv);
    const float* bias = (w == 0) ? bq : ((w == 1) ? bk : bv);

    const int m0 = blockIdx.x * 128;
    const int d0 = blockIdx.y * 128;
    const int tid = threadIdx.x;
    const int tx = tid & 15, ty = tid >> 4;
    const float* Abase = x + (size_t)b * DD * NN;

    float acc[8][8] = {};
    float4 pa[2], pb[2];
    #pragma unroll
    for (int u = 0; u < 2; ++u) {
        int idx = tid + u * 256;
        int kl = idx >> 5, m4 = (idx & 31) << 2;
        pa[u] = *(const float4*)(Abase + (size_t)kl * NN + m0 + m4);
        pb[u] = *(const float4*)(W     + (size_t)kl * DD + d0 + m4);
    }
    for (int kc = 0; kc < DD; kc += 16) {
        #pragma unroll
        for (int u = 0; u < 2; ++u) {
            int idx = tid + u * 256;
            int kl = idx >> 5, m4 = (idx & 31) << 2;
            *(float4*)&As[kl][m4] = pa[u];
            *(float4*)&Bs[kl][m4] = pb[u];
        }
        __syncthreads();
        if (kc + 16 < DD) {
            int kn = kc + 16;
            #pragma unroll
            for (int u = 0; u < 2; ++u) {
                int idx = tid + u * 256;
                int kl = idx >> 5, m4 = (idx & 31) << 2;
                pa[u] = *(const float4*)(Abase + (size_t)(kn + kl) * NN + m0 + m4);
                pb[u] = *(const float4*)(W     + (size_t)(kn + kl) * DD + d0 + m4);
            }
        }
        #pragma unroll
        for (int kk = 0; kk < 16; ++kk) {
            float a[8], bb[8];
            *(float4*)&a[0]  = *(float4*)&As[kk][ty * 8];
            *(float4*)&a[4]  = *(float4*)&As[kk][ty * 8 + 4];
            *(float4*)&bb[0] = *(float4*)&Bs[kk][tx * 8];
            *(float4*)&bb[4] = *(float4*)&Bs[kk][tx * 8 + 4];
            #pragma unroll
            for (int i = 0; i < 8; ++i)
                #pragma unroll
                for (int j = 0; j < 8; ++j)
                    acc[i][j] += a[i] * bb[j];
        }
        __syncthreads();
    }

    if (w < 2) {  // Q/K row-major [n][d]
        __half* Oh = ((w == 0) ? g_Qhi : g_Khi) + (size_t)b * NN * DD;
        __half* Ol = ((w == 0) ? g_Qlo : g_Klo) + (size_t)b * NN * DD;
        #pragma unroll
        for (int i = 0; i < 8; ++i) {
            int n = m0 + ty * 8 + i, d = d0 + tx * 8;
            float v[8];
            #pragma unroll
            for (int j = 0; j < 8; ++j) v[j] = acc[i][j] + bias[d + j];
            uint4 uh, ul; split8h(v, uh, ul);
            *(uint4*)(Oh + (size_t)n * DD + d) = uh;
            *(uint4*)(Ol + (size_t)n * DD + d) = ul;
        }
    } else {      // V transposed [d][n]
        __half* Oh = g_Vthi + (size_t)b * DD * NN;
        __half* Ol = g_Vtlo + (size_t)b * DD * NN;
        #pragma unroll
        for (int j = 0; j < 8; ++j) {
            int d = d0 + tx * 8 + j;
            float bb = bias[d];
            float v[8];
            #pragma unroll
            for (int i = 0; i < 8; ++i) v[i] = acc[i][j] + bb;
            uint4 uh, ul; split8h(v, uh, ul);
            *(uint4*)(Oh + (size_t)d * NN + m0 + ty * 8) = uh;
            *(uint4*)(Ol + (size_t)d * NN + m0 + ty * 8) = ul;
        }
    }
}

// Kernel 3: row softmax, fp32 S in, fp16 hi/lo P out.
__inline__ __device__ float warpMax(float v) {
    #pragma unroll
    for (int o = 16; o; o >>= 1) v = fmaxf(v, __shfl_xor_sync(0xffffffffu, v, o));
    return v;
}
__inline__ __device__ float warpSum(float v) {
    #pragma unroll
    for (int o = 16; o; o >>= 1) v += __shfl_xor_sync(0xffffffffu, v, o);
    return v;
}

__global__ __launch_bounds__(256) void softmax_kernel()
{
    __shared__ float red[8];
    const size_t row = blockIdx.x;
    const float* p = g_S + row * (size_t)NN;
    __half* ph = g_Phi + row * (size_t)NN;
    __half* pl = g_Plo + row * (size_t)NN;
    const int tid = threadIdx.x;
    const int lane = tid & 31, wid = tid >> 5;

    float4 v[4];
    float m = -CUDART_INF_F;
    #pragma unroll
    for (int u = 0; u < 4; ++u) {
        v[u] = *(const float4*)(p + (size_t)(tid + u * 256) * 4);
        m = fmaxf(m, fmaxf(fmaxf(v[u].x, v[u].y), fmaxf(v[u].z, v[u].w)));
    }
    m = warpMax(m);
    if (lane == 0) red[wid] = m;
    __syncthreads();
    float bm = red[0];
    #pragma unroll
    for (int i = 1; i < 8; ++i) bm = fmaxf(bm, red[i]);
    __syncthreads();

    float s = 0.f;
    #pragma unroll
    for (int u = 0; u < 4; ++u) {
        v[u].x = __expf(v[u].x - bm); v[u].y = __expf(v[u].y - bm);
        v[u].z = __expf(v[u].z - bm); v[u].w = __expf(v[u].w - bm);
        s += v[u].x + v[u].y + v[u].z + v[u].w;
    }
    s = warpSum(s);
    if (lane == 0) red[wid] = s;
    __syncthreads();
    float tot = 0.f;
    #pragma unroll
    for (int i = 0; i < 8; ++i) tot += red[i];
    float inv = 1.0f / tot;

    #pragma unroll
    for (int u = 0; u < 4; ++u) {
        size_t idx = (size_t)(tid + u * 256) * 4;
        float vv[4] = { v[u].x * inv, v[u].y * inv, v[u].z * inv, v[u].w * inv };
        __half h[4]; float lo[4];
        #pragma unroll
        for (int j = 0; j < 4; ++j) {
            h[j] = __float2half_rn(vv[j]);
            lo[j] = vv[j] - __half2float(h[j]);
        }
        *(__half2*)(ph + idx)     = __halves2half2(h[0], h[1]);
        *(__half2*)(ph + idx + 2) = __halves2half2(h[2], h[3]);
        *(__half2*)(pl + idx)     = __halves2half2(__float2half_rn(lo[0]), __float2half_rn(lo[1]));
        *(__half2*)(pl + idx + 2) = __halves2half2(__float2half_rn(lo[2]), __float2half_rn(lo[3]));
    }
}

// ---------------------------------------------------------------------------
extern "C" void kernel_launch(void* const* d_in, const int* in_sizes, int n_in,
                              void* d_out, int out_size)
{
    const float* x  = (const float*)d_in[0];
    const float* Wq = (const float*)d_in[1];
    const float* bq = (const float*)d_in[2];
    const float* Wk = (const float*)d_in[3];
    const float* bk = (const float*)d_in[4];
    const float* Wv = (const float*)d_in[5];
    const float* bv = (const float*)d_in[6];
    float* out = (float*)d_out;

    cudaFuncSetAttribute(hmma_kernel, cudaFuncAttributeMaxDynamicSharedMemorySize, SMEM_SZ);

    proj_kernel<<<dim3(NN / 128, DD / 128, BB * 3), 256>>>(x, Wq, bq, Wk, bk, Wv, bv);
    hmma_kernel<<<dim3(NN / 128, NN / 64, BB), 128, SMEM_SZ>>>(0, nullptr);  // QK -> S
    softmax_kernel<<<BB * NN, 256>>>();
    hmma_kernel<<<dim3(NN / 128, DD / 64, BB), 128, SMEM_SZ>>>(1, out);      // AV -> out
}

// round 7
// speedup vs baseline: 1.3224x; 1.2460x over previous
#include <cuda_runtime.h>
#include <cuda_fp16.h>
#include <math_constants.h>
#include <cstdint>

#define BB 4
#define NN 4096
#define DD 256

// ---------------- device scratch (allocation-free rule) ----------------
__device__ __align__(128) __half g_Qhi[(size_t)BB*NN*DD];   // [b][n][d]
__device__ __align__(128) __half g_Qlo[(size_t)BB*NN*DD];
__device__ __align__(128) __half g_Khi[(size_t)BB*NN*DD];   // [b][n][d]
__device__ __align__(128) __half g_Klo[(size_t)BB*NN*DD];
__device__ __align__(128) __half g_Vthi[(size_t)BB*DD*NN];  // [b][d][key]
__device__ __align__(128) __half g_Vtlo[(size_t)BB*DD*NN];
__device__ __align__(128) __half g_Phi[(size_t)BB*NN*NN];   // [b][q][key]
__device__ __align__(128) float  g_S [(size_t)BB*NN*NN];    // [b][q][key]

// ---------------- helpers ----------------
__device__ __forceinline__ uint32_t smem_u32(const void* p) {
    uint32_t a;
    asm("{ .reg .u64 t; cvta.to.shared.u64 t, %1; cvt.u32.u64 %0, t; }" : "=r"(a) : "l"(p));
    return a;
}

#define LDM4(r, addr) asm volatile( \
    "ldmatrix.sync.aligned.m8n8.x4.shared.b16 {%0,%1,%2,%3}, [%4];" \
    : "=r"((r)[0]), "=r"((r)[1]), "=r"((r)[2]), "=r"((r)[3]) : "r"(addr))

#define MMA16816F(c, a, b0, b1) asm volatile( \
    "mma.sync.aligned.m16n8k16.row.col.f32.f16.f16.f32 " \
    "{%0,%1,%2,%3}, {%4,%5,%6,%7}, {%8,%9}, {%0,%1,%2,%3};" \
    : "+f"((c)[0]), "+f"((c)[1]), "+f"((c)[2]), "+f"((c)[3]) \
    : "r"((a)[0]), "r"((a)[1]), "r"((a)[2]), "r"((a)[3]), "r"(b0), "r"(b1))

#define CP16(so, ga) asm volatile("cp.async.cg.shared.global [%0], [%1], 16;" \
    :: "r"(so), "l"(ga) : "memory")
#define CP_COMMIT() asm volatile("cp.async.commit_group;" ::: "memory")
#define CP_WAIT1()  asm volatile("cp.async.wait_group 1;" ::: "memory")
#define CP_WAIT2()  asm volatile("cp.async.wait_group 2;" ::: "memory")

// 64B-pitch tile with xor swizzle on 16B chunks: conflict-free for ldmatrix + cp.async
__device__ __forceinline__ uint32_t swz(uint32_t tile, int row, int chunk) {
    return tile + (uint32_t)row * 64u + ((uint32_t)((chunk ^ ((row >> 1) & 3)) & 3) << 4);
}

#define A_TILE_B 4096u     // 64 rows x 64B
#define B_TILE_B 8192u     // 128 rows x 64B

// QK: stage = Ahi+Alo+Bhi+Blo = 24KB, 3 stages
#define QK_STAGE_B 24576u
#define QK_SMEM    (3 * 24576)
// AV: stage = Vhi+Vlo+Phi = 16KB, 4 stages
#define AV_STAGE_B 16384u
#define AV_SMEM    (4 * 16384)

// ---------------------------------------------------------------------------
// QK: S[64q,128k](fp32) = Q(64,256) . K(128,256)^T, 3-term split-fp16.
// 128 threads, 4 warps (2m x 2n), warp tile 32x64. 3 CTAs/SM.
// ---------------------------------------------------------------------------
__global__ __launch_bounds__(128, 3) void qk_kernel()
{
    extern __shared__ __align__(128) char sm[];
    const int tid  = threadIdx.x;
    const int lane = tid & 31, wid = tid >> 5;
    const int wm = wid & 1, wn = wid >> 1;
    const int bx = blockIdx.x, by = blockIdx.y, bz = blockIdx.z;

    size_t ab = ((size_t)bz * NN + (size_t)by * 64) * DD;
    size_t bb = ((size_t)bz * NN + (size_t)bx * 128) * DD;
    const __half* Ahi = g_Qhi + ab;  const __half* Alo = g_Qlo + ab;
    const __half* Bhi = g_Khi + bb;  const __half* Blo = g_Klo + bb;
    float* C = g_S + (size_t)bz * NN * NN + (size_t)by * 64 * NN + (size_t)bx * 128;

    const uint32_t sbase = smem_u32(sm);

    auto load_stage = [&](int s, int ch) {
        uint32_t st = sbase + (uint32_t)s * QK_STAGE_B;
        size_t k0 = (size_t)ch * 32;
        const __half* ga[2] = { Ahi + k0, Alo + k0 };
        #pragma unroll
        for (int t2 = 0; t2 < 2; ++t2) {
            uint32_t tb = st + (uint32_t)t2 * A_TILE_B;
            #pragma unroll
            for (int i = 0; i < 2; ++i) {
                int id = tid + i * 128;
                int row = id >> 2, c = id & 3;
                CP16(swz(tb, row, c), ga[t2] + (size_t)row * DD + c * 8);
            }
        }
        const __half* gb[2] = { Bhi + k0, Blo + k0 };
        #pragma unroll
        for (int t2 = 0; t2 < 2; ++t2) {
            uint32_t tb = st + 2 * A_TILE_B + (uint32_t)t2 * B_TILE_B;
            #pragma unroll
            for (int i = 0; i < 4; ++i) {
                int id = tid + i * 128;
                int row = id >> 2, c = id & 3;
                CP16(swz(tb, row, c), gb[t2] + (size_t)row * DD + c * 8);
            }
        }
    };

    float accf[2][8][4] = {};

    auto compute = [&](int s) {
        uint32_t st  = sbase + (uint32_t)s * QK_STAGE_B;
        uint32_t tAh = st, tAl = st + A_TILE_B;
        uint32_t tBh = st + 2 * A_TILE_B, tBl = tBh + B_TILE_B;
        #pragma unroll
        for (int ks = 0; ks < 2; ++ks) {
            uint32_t ah[2][4], al[2][4], bh[4][4], bl[4][4];
            const int arow = wm * 32 + (lane & 15);
            const int achk = ks * 2 + (lane >> 4);
            #pragma unroll
            for (int mt = 0; mt < 2; ++mt) {
                LDM4(ah[mt], swz(tAh, arow + mt * 16, achk));
                LDM4(al[mt], swz(tAl, arow + mt * 16, achk));
            }
            const int brow = wn * 64 + ((lane >> 4) << 3) + (lane & 7);
            const int bchk = ks * 2 + ((lane >> 3) & 1);
            #pragma unroll
            for (int nt = 0; nt < 4; ++nt) {
                LDM4(bh[nt], swz(tBh, brow + nt * 16, bchk));
                LDM4(bl[nt], swz(tBl, brow + nt * 16, bchk));
            }
            #pragma unroll
            for (int mt = 0; mt < 2; ++mt)
                #pragma unroll
                for (int n8 = 0; n8 < 8; ++n8) {
                    const int g = n8 >> 1, h = (n8 & 1) * 2;
                    MMA16816F(accf[mt][n8], ah[mt], bh[g][h], bh[g][h+1]);
                    MMA16816F(accf[mt][n8], ah[mt], bl[g][h], bl[g][h+1]);
                    MMA16816F(accf[mt][n8], al[mt], bh[g][h], bh[g][h+1]);
                }
        }
    };

    load_stage(0, 0); CP_COMMIT();
    load_stage(1, 1); CP_COMMIT();

    const int nchunks = DD / 32;  // 8
    for (int ch = 0; ch < nchunks; ++ch) {
        CP_WAIT1();
        __syncthreads();
        if (ch + 2 < nchunks) load_stage((ch + 2) % 3, ch + 2);
        CP_COMMIT();
        compute(ch % 3);
    }

    const int r0 = wm * 32 + (lane >> 2);
    const int c0 = wn * 64 + (lane & 3) * 2;
    #pragma unroll
    for (int mt = 0; mt < 2; ++mt)
        #pragma unroll
        for (int n8 = 0; n8 < 8; ++n8) {
            float* p = C + (size_t)(r0 + mt * 16) * NN + c0 + n8 * 8;
            *(float2*)p            = make_float2(accf[mt][n8][0], accf[mt][n8][1]);
            *(float2*)(p + 8 * NN) = make_float2(accf[mt][n8][2], accf[mt][n8][3]);
        }
}

// ---------------------------------------------------------------------------
// AV: out[64d,128q](fp32) = Vt(64,4096) . P(128,4096)^T, 2-term (P fp16-only).
// 128 threads, 4 warps, warp tile 32x64. 3 CTAs/SM.
// ---------------------------------------------------------------------------
__global__ __launch_bounds__(128, 3) void av_kernel(float* __restrict__ outp)
{
    extern __shared__ __align__(128) char sm[];
    const int tid  = threadIdx.x;
    const int lane = tid & 31, wid = tid >> 5;
    const int wm = wid & 1, wn = wid >> 1;
    const int bx = blockIdx.x, by = blockIdx.y, bz = blockIdx.z;

    size_t ab = (size_t)bz * DD * NN + (size_t)by * 64 * NN;
    size_t bb = (size_t)bz * NN * NN + (size_t)bx * 128 * NN;
    const __half* Ahi = g_Vthi + ab;  const __half* Alo = g_Vtlo + ab;
    const __half* Bhi = g_Phi  + bb;
    float* C = outp + (size_t)bz * DD * NN + (size_t)by * 64 * NN + (size_t)bx * 128;

    const uint32_t sbase = smem_u32(sm);

    auto load_stage = [&](int s, int ch) {
        uint32_t st = sbase + (uint32_t)s * AV_STAGE_B;
        size_t k0 = (size_t)ch * 32;
        const __half* ga[2] = { Ahi + k0, Alo + k0 };
        #pragma unroll
        for (int t2 = 0; t2 < 2; ++t2) {
            uint32_t tb = st + (uint32_t)t2 * A_TILE_B;
            #pragma unroll
            for (int i = 0; i < 2; ++i) {
                int id = tid + i * 128;
                int row = id >> 2, c = id & 3;
                CP16(swz(tb, row, c), ga[t2] + (size_t)row * NN + c * 8);
            }
        }
        uint32_t tb = st + 2 * A_TILE_B;
        #pragma unroll
        for (int i = 0; i < 4; ++i) {
            int id = tid + i * 128;
            int row = id >> 2, c = id & 3;
            CP16(swz(tb, row, c), Bhi + k0 + (size_t)row * NN + c * 8);
        }
    };

    float accf[2][8][4] = {};

    auto compute = [&](int s) {
        uint32_t st  = sbase + (uint32_t)s * AV_STAGE_B;
        uint32_t tAh = st, tAl = st + A_TILE_B;
        uint32_t tBh = st + 2 * A_TILE_B;
        #pragma unroll
        for (int ks = 0; ks < 2; ++ks) {
            uint32_t ah[2][4], al[2][4], bh[4][4];
            const int arow = wm * 32 + (lane & 15);
            const int achk = ks * 2 + (lane >> 4);
            #pragma unroll
            for (int mt = 0; mt < 2; ++mt) {
                LDM4(ah[mt], swz(tAh, arow + mt * 16, achk));
                LDM4(al[mt], swz(tAl, arow + mt * 16, achk));
            }
            const int brow = wn * 64 + ((lane >> 4) << 3) + (lane & 7);
            const int bchk = ks * 2 + ((lane >> 3) & 1);
            #pragma unroll
            for (int nt = 0; nt < 4; ++nt)
                LDM4(bh[nt], swz(tBh, brow + nt * 16, bchk));
            #pragma unroll
            for (int mt = 0; mt < 2; ++mt)
                #pragma unroll
                for (int n8 = 0; n8 < 8; ++n8) {
                    const int g = n8 >> 1, h = (n8 & 1) * 2;
                    MMA16816F(accf[mt][n8], ah[mt], bh[g][h], bh[g][h+1]);  // P*Vhi
                    MMA16816F(accf[mt][n8], al[mt], bh[g][h], bh[g][h+1]);  // P*Vlo
                }
        }
    };

    load_stage(0, 0); CP_COMMIT();
    load_stage(1, 1); CP_COMMIT();
    load_stage(2, 2); CP_COMMIT();

    const int nchunks = NN / 32;  // 128
    for (int ch = 0; ch < nchunks; ++ch) {
        CP_WAIT2();
        __syncthreads();
        if (ch + 3 < nchunks) load_stage((ch + 3) & 3, ch + 3);
        CP_COMMIT();
        compute(ch & 3);
    }

    const int r0 = wm * 32 + (lane >> 2);
    const int c0 = wn * 64 + (lane & 3) * 2;
    #pragma unroll
    for (int mt = 0; mt < 2; ++mt)
        #pragma unroll
        for (int n8 = 0; n8 < 8; ++n8) {
            float* p = C + (size_t)(r0 + mt * 16) * NN + c0 + n8 * 8;
            *(float2*)p            = make_float2(accf[mt][n8][0], accf[mt][n8][1]);
            *(float2*)(p + 8 * NN) = make_float2(accf[mt][n8][2], accf[mt][n8][3]);
        }
}

// ---------------------------------------------------------------------------
__device__ __forceinline__ void split8h(const float* v, uint4& uh, uint4& ul) {
    __half2 h[4], l[4];
    #pragma unroll
    for (int j = 0; j < 4; ++j) {
        float a = v[2*j], b = v[2*j+1];
        __half ha = __float2half_rn(a), hb = __float2half_rn(b);
        __half la = __float2half_rn(a - __half2float(ha));
        __half lb = __float2half_rn(b - __half2float(hb));
        h[j] = __halves2half2(ha, hb);
        l[j] = __halves2half2(la, lb);
    }
    uh = *(uint4*)h; ul = *(uint4*)l;
}

// Kernel 1: fused QKV projection (SIMT fp32), fp16 hi/lo epilogues.
__global__ __launch_bounds__(256, 2) void proj_kernel(
    const float* __restrict__ x,
    const float* __restrict__ Wq, const float* __restrict__ bq,
    const float* __restrict__ Wk, const float* __restrict__ bk,
    const float* __restrict__ Wv, const float* __restrict__ bv)
{
    __shared__ float As[16][132];
    __shared__ float Bs[16][132];

    const int bz = blockIdx.z;
    const int b  = bz / 3;
    const int w  = bz % 3;
    const float* W    = (w == 0) ? Wq : ((w == 1) ? Wk : Wv);
    const float* bias = (w == 0) ? bq : ((w == 1) ? bk : bv);

    const int m0 = blockIdx.x * 128;
    const int d0 = blockIdx.y * 128;
    const int tid = threadIdx.x;
    const int tx = tid & 15, ty = tid >> 4;
    const float* Abase = x + (size_t)b * DD * NN;

    float acc[8][8] = {};
    float4 pa[2], pb[2];
    #pragma unroll
    for (int u = 0; u < 2; ++u) {
        int idx = tid + u * 256;
        int kl = idx >> 5, m4 = (idx & 31) << 2;
        pa[u] = *(const float4*)(Abase + (size_t)kl * NN + m0 + m4);
        pb[u] = *(const float4*)(W     + (size_t)kl * DD + d0 + m4);
    }
    for (int kc = 0; kc < DD; kc += 16) {
        #pragma unroll
        for (int u = 0; u < 2; ++u) {
            int idx = tid + u * 256;
            int kl = idx >> 5, m4 = (idx & 31) << 2;
            *(float4*)&As[kl][m4] = pa[u];
            *(float4*)&Bs[kl][m4] = pb[u];
        }
        __syncthreads();
        if (kc + 16 < DD) {
            int kn = kc + 16;
            #pragma unroll
            for (int u = 0; u < 2; ++u) {
                int idx = tid + u * 256;
                int kl = idx >> 5, m4 = (idx & 31) << 2;
                pa[u] = *(const float4*)(Abase + (size_t)(kn + kl) * NN + m0 + m4);
                pb[u] = *(const float4*)(W     + (size_t)(kn + kl) * DD + d0 + m4);
            }
        }
        #pragma unroll
        for (int kk = 0; kk < 16; ++kk) {
            float a[8], bb[8];
            *(float4*)&a[0]  = *(float4*)&As[kk][ty * 8];
            *(float4*)&a[4]  = *(float4*)&As[kk][ty * 8 + 4];
            *(float4*)&bb[0] = *(float4*)&Bs[kk][tx * 8];
            *(float4*)&bb[4] = *(float4*)&Bs[kk][tx * 8 + 4];
            #pragma unroll
            for (int i = 0; i < 8; ++i)
                #pragma unroll
                for (int j = 0; j < 8; ++j)
                    acc[i][j] += a[i] * bb[j];
        }
        __syncthreads();
    }

    if (w < 2) {  // Q/K row-major [n][d]
        __half* Oh = ((w == 0) ? g_Qhi : g_Khi) + (size_t)b * NN * DD;
        __half* Ol = ((w == 0) ? g_Qlo : g_Klo) + (size_t)b * NN * DD;
        #pragma unroll
        for (int i = 0; i < 8; ++i) {
            int n = m0 + ty * 8 + i, d = d0 + tx * 8;
            float v[8];
            #pragma unroll
            for (int j = 0; j < 8; ++j) v[j] = acc[i][j] + bias[d + j];
            uint4 uh, ul; split8h(v, uh, ul);
            *(uint4*)(Oh + (size_t)n * DD + d) = uh;
            *(uint4*)(Ol + (size_t)n * DD + d) = ul;
        }
    } else {      // V transposed [d][n]
        __half* Oh = g_Vthi + (size_t)b * DD * NN;
        __half* Ol = g_Vtlo + (size_t)b * DD * NN;
        #pragma unroll
        for (int j = 0; j < 8; ++j) {
            int d = d0 + tx * 8 + j;
            float bb = bias[d];
            float v[8];
            #pragma unroll
            for (int i = 0; i < 8; ++i) v[i] = acc[i][j] + bb;
            uint4 uh, ul; split8h(v, uh, ul);
            *(uint4*)(Oh + (size_t)d * NN + m0 + ty * 8) = uh;
            *(uint4*)(Ol + (size_t)d * NN + m0 + ty * 8) = ul;
        }
    }
}

// Kernel 3: row softmax, fp32 S in, fp16 P out (hi only).
__inline__ __device__ float warpMax(float v) {
    #pragma unroll
    for (int o = 16; o; o >>= 1) v = fmaxf(v, __shfl_xor_sync(0xffffffffu, v, o));
    return v;
}
__inline__ __device__ float warpSum(float v) {
    #pragma unroll
    for (int o = 16; o; o >>= 1) v += __shfl_xor_sync(0xffffffffu, v, o);
    return v;
}

__global__ __launch_bounds__(256) void softmax_kernel()
{
    __shared__ float red[8];
    const size_t row = blockIdx.x;
    const float* p = g_S + row * (size_t)NN;
    __half* ph = g_Phi + row * (size_t)NN;
    const int tid = threadIdx.x;
    const int lane = tid & 31, wid = tid >> 5;

    float4 v[4];
    float m = -CUDART_INF_F;
    #pragma unroll
    for (int u = 0; u < 4; ++u) {
        v[u] = *(const float4*)(p + (size_t)(tid + u * 256) * 4);
        m = fmaxf(m, fmaxf(fmaxf(v[u].x, v[u].y), fmaxf(v[u].z, v[u].w)));
    }
    m = warpMax(m);
    if (lane == 0) red[wid] = m;
    __syncthreads();
    float bm = red[0];
    #pragma unroll
    for (int i = 1; i < 8; ++i) bm = fmaxf(bm, red[i]);
    __syncthreads();

    float s = 0.f;
    #pragma unroll
    for (int u = 0; u < 4; ++u) {
        v[u].x = __expf(v[u].x - bm); v[u].y = __expf(v[u].y - bm);
        v[u].z = __expf(v[u].z - bm); v[u].w = __expf(v[u].w - bm);
        s += v[u].x + v[u].y + v[u].z + v[u].w;
    }
    s = warpSum(s);
    if (lane == 0) red[wid] = s;
    __syncthreads();
    float tot = 0.f;
    #pragma unroll
    for (int i = 0; i < 8; ++i) tot += red[i];
    float inv = 1.0f / tot;

    #pragma unroll
    for (int u = 0; u < 4; ++u) {
        size_t idx = (size_t)(tid + u * 256) * 4;
        *(__half2*)(ph + idx)     = __halves2half2(__float2half_rn(v[u].x * inv),
                                                   __float2half_rn(v[u].y * inv));
        *(__half2*)(ph + idx + 2) = __halves2half2(__float2half_rn(v[u].z * inv),
                                                   __float2half_rn(v[u].w * inv));
    }
}

// ---------------------------------------------------------------------------
extern "C" void kernel_launch(void* const* d_in, const int* in_sizes, int n_in,
                              void* d_out, int out_size)
{
    const float* x  = (const float*)d_in[0];
    const float* Wq = (const float*)d_in[1];
    const float* bq = (const float*)d_in[2];
    const float* Wk = (const float*)d_in[3];
    const float* bk = (const float*)d_in[4];
    const float* Wv = (const float*)d_in[5];
    const float* bv = (const float*)d_in[6];
    float* out = (float*)d_out;

    cudaFuncSetAttribute(qk_kernel, cudaFuncAttributeMaxDynamicSharedMemorySize, QK_SMEM);
    cudaFuncSetAttribute(av_kernel, cudaFuncAttributeMaxDynamicSharedMemorySize, AV_SMEM);

    proj_kernel<<<dim3(NN / 128, DD / 128, BB * 3), 256>>>(x, Wq, bq, Wk, bk, Wv, bv);
    qk_kernel<<<dim3(NN / 128, NN / 64, BB), 128, QK_SMEM>>>();
    softmax_kernel<<<BB * NN, 256>>>();
    av_kernel<<<dim3(NN / 128, DD / 64, BB), 128, AV_SMEM>>>(out);
}

// round 8
// speedup vs baseline: 1.3359x; 1.0102x over previous
#include <cuda_runtime.h>
#include <cuda_fp16.h>
#include <math_constants.h>
#include <cstdint>

#define BB 4
#define NN 4096
#define DD 256

// ---------------- device scratch (allocation-free rule) ----------------
__device__ __align__(128) __half g_Qhi[(size_t)BB*NN*DD];   // [b][n][d]
__device__ __align__(128) __half g_Qlo[(size_t)BB*NN*DD];
__device__ __align__(128) __half g_Khi[(size_t)BB*NN*DD];   // [b][n][d]
__device__ __align__(128) __half g_Klo[(size_t)BB*NN*DD];
__device__ __align__(128) __half g_Vthi[(size_t)BB*DD*NN];  // [b][d][key]
__device__ __align__(128) __half g_Vtlo[(size_t)BB*DD*NN];
__device__ __align__(128) __half g_Phi[(size_t)BB*NN*NN];   // [b][q][key]
__device__ __align__(128) float  g_S [(size_t)BB*NN*NN];    // [b][q][key]

// ---------------- helpers ----------------
__device__ __forceinline__ uint32_t smem_u32(const void* p) {
    uint32_t a;
    asm("{ .reg .u64 t; cvta.to.shared.u64 t, %1; cvt.u32.u64 %0, t; }" : "=r"(a) : "l"(p));
    return a;
}

#define LDM4(r, addr) asm volatile( \
    "ldmatrix.sync.aligned.m8n8.x4.shared.b16 {%0,%1,%2,%3}, [%4];" \
    : "=r"((r)[0]), "=r"((r)[1]), "=r"((r)[2]), "=r"((r)[3]) : "r"(addr))

#define MMA16816F(c, a, b0, b1) asm volatile( \
    "mma.sync.aligned.m16n8k16.row.col.f32.f16.f16.f32 " \
    "{%0,%1,%2,%3}, {%4,%5,%6,%7}, {%8,%9}, {%0,%1,%2,%3};" \
    : "+f"((c)[0]), "+f"((c)[1]), "+f"((c)[2]), "+f"((c)[3]) \
    : "r"((a)[0]), "r"((a)[1]), "r"((a)[2]), "r"((a)[3]), "r"(b0), "r"(b1))

#define CP16(so, ga) asm volatile("cp.async.cg.shared.global [%0], [%1], 16;" \
    :: "r"(so), "l"(ga) : "memory")
#define CP_COMMIT() asm volatile("cp.async.commit_group;" ::: "memory")
#define CP_WAIT1()  asm volatile("cp.async.wait_group 1;" ::: "memory")
#define CP_WAIT2()  asm volatile("cp.async.wait_group 2;" ::: "memory")

// packed f32x2 FMA: acc(2xf32) += a(2xf32) * b(2xf32)
#define FFMA2(acc, a, b) asm("fma.rn.f32x2 %0, %1, %2, %0;" : "+l"(acc) : "l"(a), "l"(b))
#define PACK2(dst, lo, hi) asm("mov.b64 %0, {%1, %2};" : "=l"(dst) : "r"(lo), "r"(hi))
#define UNPACK2(lo, hi, src) asm("mov.b64 {%0, %1}, %2;" : "=r"(lo), "=r"(hi) : "l"(src))

// 64B-pitch tile with xor swizzle on 16B chunks: conflict-free for ldmatrix + cp.async
__device__ __forceinline__ uint32_t swz(uint32_t tile, int row, int chunk) {
    return tile + (uint32_t)row * 64u + ((uint32_t)((chunk ^ ((row >> 1) & 3)) & 3) << 4);
}

#define T64_B  4096u     // 64 rows x 64B
#define T128_B 8192u     // 128 rows x 64B

// QK: CTA tile 128x128, stage = 4 x 8KB = 32KB, 3 stages, 256 thr, 2 CTAs/SM
#define QK_STAGE_B 32768u
#define QK_SMEM    (3 * 32768)
// AV: CTA tile 64x128, stage = Vhi+Vlo(4KB ea)+Phi(8KB) = 16KB, 4 stages, 3 CTAs/SM
#define AV_STAGE_B 16384u
#define AV_SMEM    (4 * 16384)

// ---------------------------------------------------------------------------
// QK: S[128q,128k](fp32) = Q(128,256) . K(128,256)^T, 3-term split-fp16.
// 256 threads, 8 warps (4m x 2n), warp tile 32x64. 2 CTAs/SM.
// ---------------------------------------------------------------------------
__global__ __launch_bounds__(256, 2) void qk_kernel()
{
    extern __shared__ __align__(128) char sm[];
    const int tid  = threadIdx.x;
    const int lane = tid & 31, wid = tid >> 5;
    const int wm = wid & 3, wn = wid >> 2;
    const int bx = blockIdx.x, by = blockIdx.y, bz = blockIdx.z;

    size_t ab = ((size_t)bz * NN + (size_t)by * 128) * DD;
    size_t bb = ((size_t)bz * NN + (size_t)bx * 128) * DD;
    const __half* Ahi = g_Qhi + ab;  const __half* Alo = g_Qlo + ab;
    const __half* Bhi = g_Khi + bb;  const __half* Blo = g_Klo + bb;
    float* C = g_S + (size_t)bz * NN * NN + (size_t)by * 128 * NN + (size_t)bx * 128;

    const uint32_t sbase = smem_u32(sm);

    auto load_stage = [&](int s, int ch) {
        uint32_t st = sbase + (uint32_t)s * QK_STAGE_B;
        size_t k0 = (size_t)ch * 32;
        const __half* gt[4] = { Ahi + k0, Alo + k0, Bhi + k0, Blo + k0 };
        #pragma unroll
        for (int t2 = 0; t2 < 4; ++t2) {
            uint32_t tb = st + (uint32_t)t2 * T128_B;
            #pragma unroll
            for (int i = 0; i < 2; ++i) {
                int id = tid + i * 256;
                int row = id >> 2, c = id & 3;
                CP16(swz(tb, row, c), gt[t2] + (size_t)row * DD + c * 8);
            }
        }
    };

    float accf[2][8][4] = {};

    auto compute = [&](int s) {
        uint32_t st  = sbase + (uint32_t)s * QK_STAGE_B;
        uint32_t tAh = st, tAl = st + T128_B;
        uint32_t tBh = st + 2 * T128_B, tBl = st + 3 * T128_B;
        #pragma unroll
        for (int ks = 0; ks < 2; ++ks) {
            uint32_t ah[2][4], al[2][4];
            const int arow = wm * 32 + (lane & 15);
            const int achk = ks * 2 + (lane >> 4);
            #pragma unroll
            for (int mt = 0; mt < 2; ++mt) {
                LDM4(ah[mt], swz(tAh, arow + mt * 16, achk));
                LDM4(al[mt], swz(tAl, arow + mt * 16, achk));
            }
            const int brow = wn * 64 + ((lane >> 4) << 3) + (lane & 7);
            const int bchk = ks * 2 + ((lane >> 3) & 1);
            #pragma unroll
            for (int nt = 0; nt < 4; ++nt) {
                uint32_t bh4[4], bl4[4];
                LDM4(bh4, swz(tBh, brow + nt * 16, bchk));
                LDM4(bl4, swz(tBl, brow + nt * 16, bchk));
                #pragma unroll
                for (int mt = 0; mt < 2; ++mt) {
                    MMA16816F(accf[mt][nt*2],   ah[mt], bh4[0], bh4[1]);
                    MMA16816F(accf[mt][nt*2],   ah[mt], bl4[0], bl4[1]);
                    MMA16816F(accf[mt][nt*2],   al[mt], bh4[0], bh4[1]);
                    MMA16816F(accf[mt][nt*2+1], ah[mt], bh4[2], bh4[3]);
                    MMA16816F(accf[mt][nt*2+1], ah[mt], bl4[2], bl4[3]);
                    MMA16816F(accf[mt][nt*2+1], al[mt], bh4[2], bh4[3]);
                }
            }
        }
    };

    load_stage(0, 0); CP_COMMIT();
    load_stage(1, 1); CP_COMMIT();

    const int nchunks = DD / 32;  // 8
    for (int ch = 0; ch < nchunks; ++ch) {
        CP_WAIT1();
        __syncthreads();
        if (ch + 2 < nchunks) load_stage((ch + 2) % 3, ch + 2);
        CP_COMMIT();
        compute(ch % 3);
    }

    const int r0 = wm * 32 + (lane >> 2);
    const int c0 = wn * 64 + (lane & 3) * 2;
    #pragma unroll
    for (int mt = 0; mt < 2; ++mt)
        #pragma unroll
        for (int n8 = 0; n8 < 8; ++n8) {
            float* p = C + (size_t)(r0 + mt * 16) * NN + c0 + n8 * 8;
            *(float2*)p            = make_float2(accf[mt][n8][0], accf[mt][n8][1]);
            *(float2*)(p + 8 * NN) = make_float2(accf[mt][n8][2], accf[mt][n8][3]);
        }
}

// ---------------------------------------------------------------------------
// AV: out[64d,128q](fp32) = Vt(64,4096) . P(128,4096)^T, 2-term (P fp16-only).
// 128 threads, 4 warps (2m x 2n), warp tile 32x64. 3 CTAs/SM.
// ---------------------------------------------------------------------------
__global__ __launch_bounds__(128, 3) void av_kernel(float* __restrict__ outp)
{
    extern __shared__ __align__(128) char sm[];
    const int tid  = threadIdx.x;
    const int lane = tid & 31, wid = tid >> 5;
    const int wm = wid & 1, wn = wid >> 1;
    const int bx = blockIdx.x, by = blockIdx.y, bz = blockIdx.z;

    size_t ab = (size_t)bz * DD * NN + (size_t)by * 64 * NN;
    size_t bb = (size_t)bz * NN * NN + (size_t)bx * 128 * NN;
    const __half* Ahi = g_Vthi + ab;  const __half* Alo = g_Vtlo + ab;
    const __half* Bhi = g_Phi  + bb;
    float* C = outp + (size_t)bz * DD * NN + (size_t)by * 64 * NN + (size_t)bx * 128;

    const uint32_t sbase = smem_u32(sm);

    auto load_stage = [&](int s, int ch) {
        uint32_t st = sbase + (uint32_t)s * AV_STAGE_B;
        size_t k0 = (size_t)ch * 32;
        const __half* ga[2] = { Ahi + k0, Alo + k0 };
        #pragma unroll
        for (int t2 = 0; t2 < 2; ++t2) {
            uint32_t tb = st + (uint32_t)t2 * T64_B;
            #pragma unroll
            for (int i = 0; i < 2; ++i) {
                int id = tid + i * 128;
                int row = id >> 2, c = id & 3;
                CP16(swz(tb, row, c), ga[t2] + (size_t)row * NN + c * 8);
            }
        }
        uint32_t tb = st + 2 * T64_B;
        #pragma unroll
        for (int i = 0; i < 4; ++i) {
            int id = tid + i * 128;
            int row = id >> 2, c = id & 3;
            CP16(swz(tb, row, c), Bhi + k0 + (size_t)row * NN + c * 8);
        }
    };

    float accf[2][8][4] = {};

    auto compute = [&](int s) {
        uint32_t st  = sbase + (uint32_t)s * AV_STAGE_B;
        uint32_t tAh = st, tAl = st + T64_B;
        uint32_t tBh = st + 2 * T64_B;
        #pragma unroll
        for (int ks = 0; ks < 2; ++ks) {
            uint32_t ah[2][4], al[2][4];
            const int arow = wm * 32 + (lane & 15);
            const int achk = ks * 2 + (lane >> 4);
            #pragma unroll
            for (int mt = 0; mt < 2; ++mt) {
                LDM4(ah[mt], swz(tAh, arow + mt * 16, achk));
                LDM4(al[mt], swz(tAl, arow + mt * 16, achk));
            }
            const int brow = wn * 64 + ((lane >> 4) << 3) + (lane & 7);
            const int bchk = ks * 2 + ((lane >> 3) & 1);
            #pragma unroll
            for (int nt = 0; nt < 4; ++nt) {
                uint32_t bh4[4];
                LDM4(bh4, swz(tBh, brow + nt * 16, bchk));
                #pragma unroll
                for (int mt = 0; mt < 2; ++mt) {
                    MMA16816F(accf[mt][nt*2],   ah[mt], bh4[0], bh4[1]);  // P*Vhi
                    MMA16816F(accf[mt][nt*2],   al[mt], bh4[0], bh4[1]);  // P*Vlo
                    MMA16816F(accf[mt][nt*2+1], ah[mt], bh4[2], bh4[3]);
                    MMA16816F(accf[mt][nt*2+1], al[mt], bh4[2], bh4[3]);
                }
            }
        }
    };

    load_stage(0, 0); CP_COMMIT();
    load_stage(1, 1); CP_COMMIT();
    load_stage(2, 2); CP_COMMIT();

    const int nchunks = NN / 32;  // 128
    for (int ch = 0; ch < nchunks; ++ch) {
        CP_WAIT2();
        __syncthreads();
        if (ch + 3 < nchunks) load_stage((ch + 3) & 3, ch + 3);
        CP_COMMIT();
        compute(ch & 3);
    }

    const int r0 = wm * 32 + (lane >> 2);
    const int c0 = wn * 64 + (lane & 3) * 2;
    #pragma unroll
    for (int mt = 0; mt < 2; ++mt)
        #pragma unroll
        for (int n8 = 0; n8 < 8; ++n8) {
            float* p = C + (size_t)(r0 + mt * 16) * NN + c0 + n8 * 8;
            *(float2*)p            = make_float2(accf[mt][n8][0], accf[mt][n8][1]);
            *(float2*)(p + 8 * NN) = make_float2(accf[mt][n8][2], accf[mt][n8][3]);
        }
}

// ---------------------------------------------------------------------------
__device__ __forceinline__ void split8h(const float* v, uint4& uh, uint4& ul) {
    __half2 h[4], l[4];
    #pragma unroll
    for (int j = 0; j < 4; ++j) {
        float a = v[2*j], b = v[2*j+1];
        __half ha = __float2half_rn(a), hb = __float2half_rn(b);
        __half la = __float2half_rn(a - __half2float(ha));
        __half lb = __float2half_rn(b - __half2float(hb));
        h[j] = __halves2half2(ha, hb);
        l[j] = __halves2half2(la, lb);
    }
    uh = *(uint4*)h; ul = *(uint4*)l;
}

// Kernel 1: fused QKV projection (SIMT fp32 via packed FFMA2), fp16 hi/lo out.
__global__ __launch_bounds__(256, 2) void proj_kernel(
    const float* __restrict__ x,
    const float* __restrict__ Wq, const float* __restrict__ bq,
    const float* __restrict__ Wk, const float* __restrict__ bk,
    const float* __restrict__ Wv, const float* __restrict__ bv)
{
    __shared__ float As[16][132];
    __shared__ float Bs[16][132];

    const int bz = blockIdx.z;
    const int b  = bz / 3;
    const int w  = bz % 3;
    const float* W    = (w == 0) ? Wq : ((w == 1) ? Wk : Wv);
    const float* bias = (w == 0) ? bq : ((w == 1) ? bk : bv);

    const int m0 = blockIdx.x * 128;
    const int d0 = blockIdx.y * 128;
    const int tid = threadIdx.x;
    const int tx = tid & 15, ty = tid >> 4;
    const float* Abase = x + (size_t)b * DD * NN;

    unsigned long long acc2[8][4];
    #pragma unroll
    for (int i = 0; i < 8; ++i)
        #pragma unroll
        for (int j = 0; j < 4; ++j) acc2[i][j] = 0ull;

    float4 pa[2], pb[2];
    #pragma unroll
    for (int u = 0; u < 2; ++u) {
        int idx = tid + u * 256;
        int kl = idx >> 5, m4 = (idx & 31) << 2;
        pa[u] = *(const float4*)(Abase + (size_t)kl * NN + m0 + m4);
        pb[u] = *(const float4*)(W     + (size_t)kl * DD + d0 + m4);
    }
    for (int kc = 0; kc < DD; kc += 16) {
        #pragma unroll
        for (int u = 0; u < 2; ++u) {
            int idx = tid + u * 256;
            int kl = idx >> 5, m4 = (idx & 31) << 2;
            *(float4*)&As[kl][m4] = pa[u];
            *(float4*)&Bs[kl][m4] = pb[u];
        }
        __syncthreads();
        if (kc + 16 < DD) {
            int kn = kc + 16;
            #pragma unroll
            for (int u = 0; u < 2; ++u) {
                int idx = tid + u * 256;
                int kl = idx >> 5, m4 = (idx & 31) << 2;
                pa[u] = *(const float4*)(Abase + (size_t)(kn + kl) * NN + m0 + m4);
                pb[u] = *(const float4*)(W     + (size_t)(kn + kl) * DD + d0 + m4);
            }
        }
        #pragma unroll
        for (int kk = 0; kk < 16; ++kk) {
            float a[8], bb[8];
            *(float4*)&a[0]  = *(float4*)&As[kk][ty * 8];
            *(float4*)&a[4]  = *(float4*)&As[kk][ty * 8 + 4];
            *(float4*)&bb[0] = *(float4*)&Bs[kk][tx * 8];
            *(float4*)&bb[4] = *(float4*)&Bs[kk][tx * 8 + 4];
            unsigned long long b2[4];
            #pragma unroll
            for (int j = 0; j < 4; ++j)
                PACK2(b2[j], __float_as_uint(bb[2*j]), __float_as_uint(bb[2*j+1]));
            #pragma unroll
            for (int i = 0; i < 8; ++i) {
                unsigned long long a2;
                PACK2(a2, __float_as_uint(a[i]), __float_as_uint(a[i]));
                #pragma unroll
                for (int j = 0; j < 4; ++j)
                    FFMA2(acc2[i][j], a2, b2[j]);
            }
        }
        __syncthreads();
    }

    // unpack accumulators: acc[i][j]
    float acc[8][8];
    #pragma unroll
    for (int i = 0; i < 8; ++i)
        #pragma unroll
        for (int j = 0; j < 4; ++j) {
            uint32_t lo, hi;
            UNPACK2(lo, hi, acc2[i][j]);
            acc[i][2*j]   = __uint_as_float(lo);
            acc[i][2*j+1] = __uint_as_float(hi);
        }

    if (w < 2) {  // Q/K row-major [n][d]
        __half* Oh = ((w == 0) ? g_Qhi : g_Khi) + (size_t)b * NN * DD;
        __half* Ol = ((w == 0) ? g_Qlo : g_Klo) + (size_t)b * NN * DD;
        #pragma unroll
        for (int i = 0; i < 8; ++i) {
            int n = m0 + ty * 8 + i, d = d0 + tx * 8;
            float v[8];
            #pragma unroll
            for (int j = 0; j < 8; ++j) v[j] = acc[i][j] + bias[d + j];
            uint4 uh, ul; split8h(v, uh, ul);
            *(uint4*)(Oh + (size_t)n * DD + d) = uh;
            *(uint4*)(Ol + (size_t)n * DD + d) = ul;
        }
    } else {      // V transposed [d][n]
        __half* Oh = g_Vthi + (size_t)b * DD * NN;
        __half* Ol = g_Vtlo + (size_t)b * DD * NN;
        #pragma unroll
        for (int j = 0; j < 8; ++j) {
            int d = d0 + tx * 8 + j;
            float bb = bias[d];
            float v[8];
            #pragma unroll
            for (int i = 0; i < 8; ++i) v[i] = acc[i][j] + bb;
            uint4 uh, ul; split8h(v, uh, ul);
            *(uint4*)(Oh + (size_t)d * NN + m0 + ty * 8) = uh;
            *(uint4*)(Ol + (size_t)d * NN + m0 + ty * 8) = ul;
        }
    }
}

// Kernel 3: row softmax, fp32 S in, fp16 P out (hi only).
__inline__ __device__ float warpMax(float v) {
    #pragma unroll
    for (int o = 16; o; o >>= 1) v = fmaxf(v, __shfl_xor_sync(0xffffffffu, v, o));
    return v;
}
__inline__ __device__ float warpSum(float v) {
    #pragma unroll
    for (int o = 16; o; o >>= 1) v += __shfl_xor_sync(0xffffffffu, v, o);
    return v;
}

__global__ __launch_bounds__(256) void softmax_kernel()
{
    __shared__ float red[8];
    const size_t row = blockIdx.x;
    const float* p = g_S + row * (size_t)NN;
    __half* ph = g_Phi + row * (size_t)NN;
    const int tid = threadIdx.x;
    const int lane = tid & 31, wid = tid >> 5;

    float4 v[4];
    float m = -CUDART_INF_F;
    #pragma unroll
    for (int u = 0; u < 4; ++u) {
        v[u] = *(const float4*)(p + (size_t)(tid + u * 256) * 4);
        m = fmaxf(m, fmaxf(fmaxf(v[u].x, v[u].y), fmaxf(v[u].z, v[u].w)));
    }
    m = warpMax(m);
    if (lane == 0) red[wid] = m;
    __syncthreads();
    float bm = red[0];
    #pragma unroll
    for (int i = 1; i < 8; ++i) bm = fmaxf(bm, red[i]);
    __syncthreads();

    float s = 0.f;
    #pragma unroll
    for (int u = 0; u < 4; ++u) {
        v[u].x = __expf(v[u].x - bm); v[u].y = __expf(v[u].y - bm);
        v[u].z = __expf(v[u].z - bm); v[u].w = __expf(v[u].w - bm);
        s += v[u].x + v[u].y + v[u].z + v[u].w;
    }
    s = warpSum(s);
    if (lane == 0) red[wid] = s;
    __syncthreads();
    float tot = 0.f;
    #pragma unroll
    for (int i = 0; i < 8; ++i) tot += red[i];
    float inv = 1.0f / tot;

    #pragma unroll
    for (int u = 0; u < 4; ++u) {
        size_t idx = (size_t)(tid + u * 256) * 4;
        *(__half2*)(ph + idx)     = __halves2half2(__float2half_rn(v[u].x * inv),
                                                   __float2half_rn(v[u].y * inv));
        *(__half2*)(ph + idx + 2) = __halves2half2(__float2half_rn(v[u].z * inv),
                                                   __float2half_rn(v[u].w * inv));
    }
}

// ---------------------------------------------------------------------------
extern "C" void kernel_launch(void* const* d_in, const int* in_sizes, int n_in,
                              void* d_out, int out_size)
{
    const float* x  = (const float*)d_in[0];
    const float* Wq = (const float*)d_in[1];
    const float* bq = (const float*)d_in[2];
    const float* Wk = (const float*)d_in[3];
    const float* bk = (const float*)d_in[4];
    const float* Wv = (const float*)d_in[5];
    const float* bv = (const float*)d_in[6];
    float* out = (float*)d_out;

    cudaFuncSetAttribute(qk_kernel, cudaFuncAttributeMaxDynamicSharedMemorySize, QK_SMEM);
    cudaFuncSetAttribute(av_kernel, cudaFuncAttributeMaxDynamicSharedMemorySize, AV_SMEM);

    proj_kernel<<<dim3(NN / 128, DD / 128, BB * 3), 256>>>(x, Wq, bq, Wk, bk, Wv, bv);
    qk_kernel<<<dim3(NN / 128, NN / 128, BB), 256, QK_SMEM>>>();
    softmax_kernel<<<BB * NN, 256>>>();
    av_kernel<<<dim3(NN / 128, DD / 64, BB), 128, AV_SMEM>>>(out);
}

// round 9
// speedup vs baseline: 1.3620x; 1.0196x over previous
#include <cuda_runtime.h>
#include <cuda_fp16.h>
#include <math_constants.h>
#include <cstdint>

#define BB 4
#define NN 4096
#define DD 256

// ---------------- device scratch (allocation-free rule) ----------------
__device__ __align__(128) __half g_Qhi[(size_t)BB*NN*DD];   // [b][n][d]
__device__ __align__(128) __half g_Qlo[(size_t)BB*NN*DD];
__device__ __align__(128) __half g_Khi[(size_t)BB*NN*DD];   // [b][n][d]
__device__ __align__(128) __half g_Klo[(size_t)BB*NN*DD];
__device__ __align__(128) __half g_Vthi[(size_t)BB*DD*NN];  // [b][d][key]
__device__ __align__(128) __half g_Vtlo[(size_t)BB*DD*NN];
__device__ __align__(128) __half g_Phi[(size_t)BB*NN*NN];   // [b][q][key]
__device__ __align__(128) float  g_S [(size_t)BB*NN*NN];    // [b][q][key]

// ---------------- helpers ----------------
__device__ __forceinline__ uint32_t smem_u32(const void* p) {
    uint32_t a;
    asm("{ .reg .u64 t; cvta.to.shared.u64 t, %1; cvt.u32.u64 %0, t; }" : "=r"(a) : "l"(p));
    return a;
}

#define LDM4(r, addr) asm volatile( \
    "ldmatrix.sync.aligned.m8n8.x4.shared.b16 {%0,%1,%2,%3}, [%4];" \
    : "=r"((r)[0]), "=r"((r)[1]), "=r"((r)[2]), "=r"((r)[3]) : "r"(addr))

#define MMA16816F(c, a, b0, b1) asm volatile( \
    "mma.sync.aligned.m16n8k16.row.col.f32.f16.f16.f32 " \
    "{%0,%1,%2,%3}, {%4,%5,%6,%7}, {%8,%9}, {%0,%1,%2,%3};" \
    : "+f"((c)[0]), "+f"((c)[1]), "+f"((c)[2]), "+f"((c)[3]) \
    : "r"((a)[0]), "r"((a)[1]), "r"((a)[2]), "r"((a)[3]), "r"(b0), "r"(b1))

#define CP16(so, ga) asm volatile("cp.async.cg.shared.global [%0], [%1], 16;" \
    :: "r"(so), "l"(ga) : "memory")
#define CP_COMMIT() asm volatile("cp.async.commit_group;" ::: "memory")
#define CP_WAIT1()  asm volatile("cp.async.wait_group 1;" ::: "memory")
#define CP_WAIT2()  asm volatile("cp.async.wait_group 2;" ::: "memory")

// packed f32x2 FMA: acc(2xf32) += a(2xf32) * b(2xf32)
#define FFMA2(acc, a, b) asm("fma.rn.f32x2 %0, %1, %2, %0;" : "+l"(acc) : "l"(a), "l"(b))
#define PACK2(dst, lo, hi) asm("mov.b64 %0, {%1, %2};" : "=l"(dst) : "r"(lo), "r"(hi))
#define UNPACK2(lo, hi, src) asm("mov.b64 {%0, %1}, %2;" : "=r"(lo), "=r"(hi) : "l"(src))

// 64B-pitch tile with xor swizzle on 16B chunks: conflict-free for ldmatrix + cp.async
__device__ __forceinline__ uint32_t swz(uint32_t tile, int row, int chunk) {
    return tile + (uint32_t)row * 64u + ((uint32_t)((chunk ^ ((row >> 1) & 3)) & 3) << 4);
}

#define T64_B  4096u     // 64 rows x 64B
#define T128_B 8192u     // 128 rows x 64B

// QK: CTA tile 128x128, stage = 4 x 8KB = 32KB, 3 stages, 256 thr, 2 CTAs/SM
#define QK_STAGE_B 32768u
#define QK_SMEM    (3 * 32768)
// AV: CTA tile 64d x 64q, stage = Vhi+Vlo+Phi = 3 x 4KB = 12KB, 4 stages, 4 CTAs/SM
#define AV_STAGE_B 12288u
#define AV_SMEM    (4 * 12288)

// ---------------------------------------------------------------------------
// QK: S[128q,128k](fp32) = Q(128,256) . K(128,256)^T, 3-term split-fp16.
// 256 threads, 8 warps (4m x 2n), warp tile 32x64. 2 CTAs/SM.
// ---------------------------------------------------------------------------
__global__ __launch_bounds__(256, 2) void qk_kernel()
{
    extern __shared__ __align__(128) char sm[];
    const int tid  = threadIdx.x;
    const int lane = tid & 31, wid = tid >> 5;
    const int wm = wid & 3, wn = wid >> 2;
    const int bx = blockIdx.x, by = blockIdx.y, bz = blockIdx.z;

    size_t ab = ((size_t)bz * NN + (size_t)by * 128) * DD;
    size_t bb = ((size_t)bz * NN + (size_t)bx * 128) * DD;
    const __half* Ahi = g_Qhi + ab;  const __half* Alo = g_Qlo + ab;
    const __half* Bhi = g_Khi + bb;  const __half* Blo = g_Klo + bb;
    float* C = g_S + (size_t)bz * NN * NN + (size_t)by * 128 * NN + (size_t)bx * 128;

    const uint32_t sbase = smem_u32(sm);

    auto load_stage = [&](int s, int ch) {
        uint32_t st = sbase + (uint32_t)s * QK_STAGE_B;
        size_t k0 = (size_t)ch * 32;
        const __half* gt[4] = { Ahi + k0, Alo + k0, Bhi + k0, Blo + k0 };
        #pragma unroll
        for (int t2 = 0; t2 < 4; ++t2) {
            uint32_t tb = st + (uint32_t)t2 * T128_B;
            #pragma unroll
            for (int i = 0; i < 2; ++i) {
                int id = tid + i * 256;
                int row = id >> 2, c = id & 3;
                CP16(swz(tb, row, c), gt[t2] + (size_t)row * DD + c * 8);
            }
        }
    };

    float accf[2][8][4] = {};

    auto compute = [&](int s) {
        uint32_t st  = sbase + (uint32_t)s * QK_STAGE_B;
        uint32_t tAh = st, tAl = st + T128_B;
        uint32_t tBh = st + 2 * T128_B, tBl = st + 3 * T128_B;
        #pragma unroll
        for (int ks = 0; ks < 2; ++ks) {
            uint32_t ah[2][4], al[2][4];
            const int arow = wm * 32 + (lane & 15);
            const int achk = ks * 2 + (lane >> 4);
            #pragma unroll
            for (int mt = 0; mt < 2; ++mt) {
                LDM4(ah[mt], swz(tAh, arow + mt * 16, achk));
                LDM4(al[mt], swz(tAl, arow + mt * 16, achk));
            }
            const int brow = wn * 64 + ((lane >> 4) << 3) + (lane & 7);
            const int bchk = ks * 2 + ((lane >> 3) & 1);
            #pragma unroll
            for (int nt = 0; nt < 4; ++nt) {
                uint32_t bh4[4], bl4[4];
                LDM4(bh4, swz(tBh, brow + nt * 16, bchk));
                LDM4(bl4, swz(tBl, brow + nt * 16, bchk));
                #pragma unroll
                for (int mt = 0; mt < 2; ++mt) {
                    MMA16816F(accf[mt][nt*2],   ah[mt], bh4[0], bh4[1]);
                    MMA16816F(accf[mt][nt*2],   ah[mt], bl4[0], bl4[1]);
                    MMA16816F(accf[mt][nt*2],   al[mt], bh4[0], bh4[1]);
                    MMA16816F(accf[mt][nt*2+1], ah[mt], bh4[2], bh4[3]);
                    MMA16816F(accf[mt][nt*2+1], ah[mt], bl4[2], bl4[3]);
                    MMA16816F(accf[mt][nt*2+1], al[mt], bh4[2], bh4[3]);
                }
            }
        }
    };

    load_stage(0, 0); CP_COMMIT();
    load_stage(1, 1); CP_COMMIT();

    const int nchunks = DD / 32;  // 8
    for (int ch = 0; ch < nchunks; ++ch) {
        CP_WAIT1();
        __syncthreads();
        if (ch + 2 < nchunks) load_stage((ch + 2) % 3, ch + 2);
        CP_COMMIT();
        compute(ch % 3);
    }

    const int r0 = wm * 32 + (lane >> 2);
    const int c0 = wn * 64 + (lane & 3) * 2;
    #pragma unroll
    for (int mt = 0; mt < 2; ++mt)
        #pragma unroll
        for (int n8 = 0; n8 < 8; ++n8) {
            float* p = C + (size_t)(r0 + mt * 16) * NN + c0 + n8 * 8;
            *(float2*)p            = make_float2(accf[mt][n8][0], accf[mt][n8][1]);
            *(float2*)(p + 8 * NN) = make_float2(accf[mt][n8][2], accf[mt][n8][3]);
        }
}

// ---------------------------------------------------------------------------
// AV: out[64d,64q](fp32) = Vt(64,4096) . P(64,4096)^T, 2-term (P fp16-only).
// 128 threads, 4 warps (2m x 2n), warp tile 32x32. 4 CTAs/SM -> 1.73 waves.
// ---------------------------------------------------------------------------
__global__ __launch_bounds__(128, 4) void av_kernel(float* __restrict__ outp)
{
    extern __shared__ __align__(128) char sm[];
    const int tid  = threadIdx.x;
    const int lane = tid & 31, wid = tid >> 5;
    const int wm = wid & 1, wn = wid >> 1;
    const int bx = blockIdx.x, by = blockIdx.y, bz = blockIdx.z;

    size_t ab = (size_t)bz * DD * NN + (size_t)by * 64 * NN;
    size_t bb = (size_t)bz * NN * NN + (size_t)bx * 64 * NN;
    const __half* Ahi = g_Vthi + ab;  const __half* Alo = g_Vtlo + ab;
    const __half* Bhi = g_Phi  + bb;
    float* C = outp + (size_t)bz * DD * NN + (size_t)by * 64 * NN + (size_t)bx * 64;

    const uint32_t sbase = smem_u32(sm);

    auto load_stage = [&](int s, int ch) {
        uint32_t st = sbase + (uint32_t)s * AV_STAGE_B;
        size_t k0 = (size_t)ch * 32;
        const __half* gt[3] = { Ahi + k0, Alo + k0, Bhi + k0 };
        #pragma unroll
        for (int t2 = 0; t2 < 3; ++t2) {
            uint32_t tb = st + (uint32_t)t2 * T64_B;
            #pragma unroll
            for (int i = 0; i < 2; ++i) {
                int id = tid + i * 128;
                int row = id >> 2, c = id & 3;
                CP16(swz(tb, row, c), gt[t2] + (size_t)row * NN + c * 8);
            }
        }
    };

    float accf[2][4][4] = {};

    auto compute = [&](int s) {
        uint32_t st  = sbase + (uint32_t)s * AV_STAGE_B;
        uint32_t tAh = st, tAl = st + T64_B;
        uint32_t tBh = st + 2 * T64_B;
        #pragma unroll
        for (int ks = 0; ks < 2; ++ks) {
            uint32_t ah[2][4], al[2][4];
            const int arow = wm * 32 + (lane & 15);
            const int achk = ks * 2 + (lane >> 4);
            #pragma unroll
            for (int mt = 0; mt < 2; ++mt) {
                LDM4(ah[mt], swz(tAh, arow + mt * 16, achk));
                LDM4(al[mt], swz(tAl, arow + mt * 16, achk));
            }
            const int brow = wn * 32 + ((lane >> 4) << 3) + (lane & 7);
            const int bchk = ks * 2 + ((lane >> 3) & 1);
            #pragma unroll
            for (int nt = 0; nt < 2; ++nt) {
                uint32_t bh4[4];
                LDM4(bh4, swz(tBh, brow + nt * 16, bchk));
                #pragma unroll
                for (int mt = 0; mt < 2; ++mt) {
                    MMA16816F(accf[mt][nt*2],   ah[mt], bh4[0], bh4[1]);  // P*Vhi
                    MMA16816F(accf[mt][nt*2],   al[mt], bh4[0], bh4[1]);  // P*Vlo
                    MMA16816F(accf[mt][nt*2+1], ah[mt], bh4[2], bh4[3]);
                    MMA16816F(accf[mt][nt*2+1], al[mt], bh4[2], bh4[3]);
                }
            }
        }
    };

    load_stage(0, 0); CP_COMMIT();
    load_stage(1, 1); CP_COMMIT();
    load_stage(2, 2); CP_COMMIT();

    const int nchunks = NN / 32;  // 128
    for (int ch = 0; ch < nchunks; ++ch) {
        CP_WAIT2();
        __syncthreads();
        if (ch + 3 < nchunks) load_stage((ch + 3) & 3, ch + 3);
        CP_COMMIT();
        compute(ch & 3);
    }

    const int r0 = wm * 32 + (lane >> 2);
    const int c0 = wn * 32 + (lane & 3) * 2;
    #pragma unroll
    for (int mt = 0; mt < 2; ++mt)
        #pragma unroll
        for (int n8 = 0; n8 < 4; ++n8) {
            float* p = C + (size_t)(r0 + mt * 16) * NN + c0 + n8 * 8;
            *(float2*)p            = make_float2(accf[mt][n8][0], accf[mt][n8][1]);
            *(float2*)(p + 8 * NN) = make_float2(accf[mt][n8][2], accf[mt][n8][3]);
        }
}

// ---------------------------------------------------------------------------
__device__ __forceinline__ void split8h(const float* v, uint4& uh, uint4& ul) {
    __half2 h[4], l[4];
    #pragma unroll
    for (int j = 0; j < 4; ++j) {
        float a = v[2*j], b = v[2*j+1];
        __half ha = __float2half_rn(a), hb = __float2half_rn(b);
        __half la = __float2half_rn(a - __half2float(ha));
        __half lb = __float2half_rn(b - __half2float(hb));
        h[j] = __halves2half2(ha, hb);
        l[j] = __halves2half2(la, lb);
    }
    uh = *(uint4*)h; ul = *(uint4*)l;
}

// Kernel 1: fused QKV projection (SIMT fp32 via packed FFMA2), fp16 hi/lo out.
__global__ __launch_bounds__(256, 2) void proj_kernel(
    const float* __restrict__ x,
    const float* __restrict__ Wq, const float* __restrict__ bq,
    const float* __restrict__ Wk, const float* __restrict__ bk,
    const float* __restrict__ Wv, const float* __restrict__ bv)
{
    __shared__ float As[16][132];
    __shared__ float Bs[16][132];

    const int bz = blockIdx.z;
    const int b  = bz / 3;
    const int w  = bz % 3;
    const float* W    = (w == 0) ? Wq : ((w == 1) ? Wk : Wv);
    const float* bias = (w == 0) ? bq : ((w == 1) ? bk : bv);

    const int m0 = blockIdx.x * 128;
    const int d0 = blockIdx.y * 128;
    const int tid = threadIdx.x;
    const int tx = tid & 15, ty = tid >> 4;
    const float* Abase = x + (size_t)b * DD * NN;

    unsigned long long acc2[8][4];
    #pragma unroll
    for (int i = 0; i < 8; ++i)
        #pragma unroll
        for (int j = 0; j < 4; ++j) acc2[i][j] = 0ull;

    float4 pa[2], pb[2];
    #pragma unroll
    for (int u = 0; u < 2; ++u) {
        int idx = tid + u * 256;
        int kl = idx >> 5, m4 = (idx & 31) << 2;
        pa[u] = *(const float4*)(Abase + (size_t)kl * NN + m0 + m4);
        pb[u] = *(const float4*)(W     + (size_t)kl * DD + d0 + m4);
    }
    for (int kc = 0; kc < DD; kc += 16) {
        #pragma unroll
        for (int u = 0; u < 2; ++u) {
            int idx = tid + u * 256;
            int kl = idx >> 5, m4 = (idx & 31) << 2;
            *(float4*)&As[kl][m4] = pa[u];
            *(float4*)&Bs[kl][m4] = pb[u];
        }
        __syncthreads();
        if (kc + 16 < DD) {
            int kn = kc + 16;
            #pragma unroll
            for (int u = 0; u < 2; ++u) {
                int idx = tid + u * 256;
                int kl = idx >> 5, m4 = (idx & 31) << 2;
                pa[u] = *(const float4*)(Abase + (size_t)(kn + kl) * NN + m0 + m4);
                pb[u] = *(const float4*)(W     + (size_t)(kn + kl) * DD + d0 + m4);
            }
        }
        #pragma unroll
        for (int kk = 0; kk < 16; ++kk) {
            float a[8], bb[8];
            *(float4*)&a[0]  = *(float4*)&As[kk][ty * 8];
            *(float4*)&a[4]  = *(float4*)&As[kk][ty * 8 + 4];
            *(float4*)&bb[0] = *(float4*)&Bs[kk][tx * 8];
            *(float4*)&bb[4] = *(float4*)&Bs[kk][tx * 8 + 4];
            unsigned long long b2[4];
            #pragma unroll
            for (int j = 0; j < 4; ++j)
                PACK2(b2[j], __float_as_uint(bb[2*j]), __float_as_uint(bb[2*j+1]));
            #pragma unroll
            for (int i = 0; i < 8; ++i) {
                unsigned long long a2;
                PACK2(a2, __float_as_uint(a[i]), __float_as_uint(a[i]));
                #pragma unroll
                for (int j = 0; j < 4; ++j)
                    FFMA2(acc2[i][j], a2, b2[j]);
            }
        }
        __syncthreads();
    }

    float acc[8][8];
    #pragma unroll
    for (int i = 0; i < 8; ++i)
        #pragma unroll
        for (int j = 0; j < 4; ++j) {
            uint32_t lo, hi;
            UNPACK2(lo, hi, acc2[i][j]);
            acc[i][2*j]   = __uint_as_float(lo);
            acc[i][2*j+1] = __uint_as_float(hi);
        }

    if (w < 2) {  // Q/K row-major [n][d]
        __half* Oh = ((w == 0) ? g_Qhi : g_Khi) + (size_t)b * NN * DD;
        __half* Ol = ((w == 0) ? g_Qlo : g_Klo) + (size_t)b * NN * DD;
        #pragma unroll
        for (int i = 0; i < 8; ++i) {
            int n = m0 + ty * 8 + i, d = d0 + tx * 8;
            float v[8];
            #pragma unroll
            for (int j = 0; j < 8; ++j) v[j] = acc[i][j] + bias[d + j];
            uint4 uh, ul; split8h(v, uh, ul);
            *(uint4*)(Oh + (size_t)n * DD + d) = uh;
            *(uint4*)(Ol + (size_t)n * DD + d) = ul;
        }
    } else {      // V transposed [d][n]
        __half* Oh = g_Vthi + (size_t)b * DD * NN;
        __half* Ol = g_Vtlo + (size_t)b * DD * NN;
        #pragma unroll
        for (int j = 0; j < 8; ++j) {
            int d = d0 + tx * 8 + j;
            float bb = bias[d];
            float v[8];
            #pragma unroll
            for (int i = 0; i < 8; ++i) v[i] = acc[i][j] + bb;
            uint4 uh, ul; split8h(v, uh, ul);
            *(uint4*)(Oh + (size_t)d * NN + m0 + ty * 8) = uh;
            *(uint4*)(Ol + (size_t)d * NN + m0 + ty * 8) = ul;
        }
    }
}

// Kernel 3: row softmax, fp32 S in, fp16 P out (hi only).
__inline__ __device__ float warpMax(float v) {
    #pragma unroll
    for (int o = 16; o; o >>= 1) v = fmaxf(v, __shfl_xor_sync(0xffffffffu, v, o));
    return v;
}
__inline__ __device__ float warpSum(float v) {
    #pragma unroll
    for (int o = 16; o; o >>= 1) v += __shfl_xor_sync(0xffffffffu, v, o);
    return v;
}

__global__ __launch_bounds__(256) void softmax_kernel()
{
    __shared__ float red[8];
    const size_t row = blockIdx.x;
    const float* p = g_S + row * (size_t)NN;
    __half* ph = g_Phi + row * (size_t)NN;
    const int tid = threadIdx.x;
    const int lane = tid & 31, wid = tid >> 5;

    float4 v[4];
    float m = -CUDART_INF_F;
    #pragma unroll
    for (int u = 0; u < 4; ++u) {
        v[u] = *(const float4*)(p + (size_t)(tid + u * 256) * 4);
        m = fmaxf(m, fmaxf(fmaxf(v[u].x, v[u].y), fmaxf(v[u].z, v[u].w)));
    }
    m = warpMax(m);
    if (lane == 0) red[wid] = m;
    __syncthreads();
    float bm = red[0];
    #pragma unroll
    for (int i = 1; i < 8; ++i) bm = fmaxf(bm, red[i]);
    __syncthreads();

    float s = 0.f;
    #pragma unroll
    for (int u = 0; u < 4; ++u) {
        v[u].x = __expf(v[u].x - bm); v[u].y = __expf(v[u].y - bm);
        v[u].z = __expf(v[u].z - bm); v[u].w = __expf(v[u].w - bm);
        s += v[u].x + v[u].y + v[u].z + v[u].w;
    }
    s = warpSum(s);
    if (lane == 0) red[wid] = s;
    __syncthreads();
    float tot = 0.f;
    #pragma unroll
    for (int i = 0; i < 8; ++i) tot += red[i];
    float inv = 1.0f / tot;

    #pragma unroll
    for (int u = 0; u < 4; ++u) {
        size_t idx = (size_t)(tid + u * 256) * 4;
        *(__half2*)(ph + idx)     = __halves2half2(__float2half_rn(v[u].x * inv),
                                                   __float2half_rn(v[u].y * inv));
        *(__half2*)(ph + idx + 2) = __halves2half2(__float2half_rn(v[u].z * inv),
                                                   __float2half_rn(v[u].w * inv));
    }
}

// ---------------------------------------------------------------------------
extern "C" void kernel_launch(void* const* d_in, const int* in_sizes, int n_in,
                              void* d_out, int out_size)
{
    const float* x  = (const float*)d_in[0];
    const float* Wq = (const float*)d_in[1];
    const float* bq = (const float*)d_in[2];
    const float* Wk = (const float*)d_in[3];
    const float* bk = (const float*)d_in[4];
    const float* Wv = (const float*)d_in[5];
    const float* bv = (const float*)d_in[6];
    float* out = (float*)d_out;

    cudaFuncSetAttribute(qk_kernel, cudaFuncAttributeMaxDynamicSharedMemorySize, QK_SMEM);
    cudaFuncSetAttribute(av_kernel, cudaFuncAttributeMaxDynamicSharedMemorySize, AV_SMEM);

    proj_kernel<<<dim3(NN / 128, DD / 128, BB * 3), 256>>>(x, Wq, bq, Wk, bk, Wv, bv);
    qk_kernel<<<dim3(NN / 128, NN / 128, BB), 256, QK_SMEM>>>();
    softmax_kernel<<<BB * NN, 256>>>();
    av_kernel<<<dim3(NN / 64, DD / 64, BB), 128, AV_SMEM>>>(out);
}